// round 3
// baseline (speedup 1.0000x reference)
#include <cuda_runtime.h>
#include <cstdint>
#include <cmath>

#define NN 100000
#define NE 1600000
#define NBLK_SCAN ((NN + 1023) / 1024)   // 98

// ---------------- static device scratch (no allocation allowed) ----------------
__device__ int   g_deg[NN];
__device__ int   g_rowoff[NN + 1];
__device__ int   g_cursor[NN];
__device__ int   g_csr[NE];
__device__ int   g_bsum[128];
__device__ float g_invdeg[NN];
__device__ float g_h[(size_t)NN * 128];
__device__ float g_selfp[(size_t)NN * 128];
__device__ float g_tmp[(size_t)NN * 128];

// ---------------- preprocessing kernels ----------------
__global__ void k_zero_deg() {
    int i = blockIdx.x * blockDim.x + threadIdx.x;
    if (i < NN) g_deg[i] = 0;
}

__global__ void k_hist(const int* __restrict__ dst) {
    int e = blockIdx.x * blockDim.x + threadIdx.x;
    if (e < NE) atomicAdd(&g_deg[dst[e]], 1);
}

__global__ void k_scan_partial() {
    __shared__ int wsum[8];
    int t = threadIdx.x;
    int base = blockIdx.x * 1024 + t * 4;
    int s = 0;
#pragma unroll
    for (int i = 0; i < 4; i++) {
        int idx = base + i;
        if (idx < NN) s += g_deg[idx];
    }
#pragma unroll
    for (int o = 16; o; o >>= 1) s += __shfl_xor_sync(0xffffffffu, s, o);
    if ((t & 31) == 0) wsum[t >> 5] = s;
    __syncthreads();
    if (t == 0) {
        int tot = 0;
#pragma unroll
        for (int i = 0; i < 8; i++) tot += wsum[i];
        g_bsum[blockIdx.x] = tot;
    }
}

__global__ void k_scan_bsums() {
    if (threadIdx.x == 0 && blockIdx.x == 0) {
        int acc = 0;
        for (int i = 0; i < NBLK_SCAN; i++) { int v = g_bsum[i]; g_bsum[i] = acc; acc += v; }
    }
}

__global__ void k_scan_final() {
    __shared__ int wsum[8];
    int t = threadIdx.x;
    int base = blockIdx.x * 1024 + t * 4;
    int v[4];
    int s = 0;
#pragma unroll
    for (int i = 0; i < 4; i++) {
        int idx = base + i;
        v[i] = (idx < NN) ? g_deg[idx] : 0;
        s += v[i];
    }
    int lane = t & 31, wid = t >> 5;
    int inc = s;
#pragma unroll
    for (int o = 1; o < 32; o <<= 1) {
        int y = __shfl_up_sync(0xffffffffu, inc, o);
        if (lane >= o) inc += y;
    }
    if (lane == 31) wsum[wid] = inc;
    __syncthreads();
    if (t == 0) {
        int acc = 0;
#pragma unroll
        for (int i = 0; i < 8; i++) { int x = wsum[i]; wsum[i] = acc; acc += x; }
    }
    __syncthreads();
    int excl = g_bsum[blockIdx.x] + wsum[wid] + (inc - s);
#pragma unroll
    for (int i = 0; i < 4; i++) {
        int idx = base + i;
        if (idx < NN) {
            g_rowoff[idx] = excl;
            g_cursor[idx] = excl;
            g_invdeg[idx] = 1.0f / fmaxf((float)v[i], 1.0f);
            excl += v[i];
        }
    }
    if (blockIdx.x == 0 && t == 0) g_rowoff[NN] = NE;
}

__global__ void k_scatter(const int* __restrict__ src, const int* __restrict__ dst) {
    int e = blockIdx.x * blockDim.x + threadIdx.x;
    if (e < NE) {
        int p = atomicAdd(&g_cursor[dst[e]], 1);
        g_csr[p] = src[e];
    }
}

// ---------------- dual SGEMM ----------------
// One launch per layer. blockIdx.x == 0 : g_selfp[M,N] = A @ Bs + bias
//                       blockIdx.x == 1 : g_tmp  [M,N] = A @ Bn
// A is the layer input: template ASRC==0 -> param pointer (x), ASRC==1 -> g_h.
// BM=128, BN=N(<=128), BK=8, 256 threads, 8x8 micro-tile.
template <int ASRC>
__global__ __launch_bounds__(256) void k_gemm_dual(
    const float* __restrict__ Aparam,
    const float* __restrict__ Bs, const float* __restrict__ Bn,
    const float* __restrict__ bias, int N) {
    const int K = 128;
    const int M = NN;
    const float* A = (ASRC == 0) ? Aparam : g_h;
    const float* B = (blockIdx.x == 0) ? Bs : Bn;
    float* C       = (blockIdx.x == 0) ? g_selfp : g_tmp;
    bool use_bias  = (blockIdx.x == 0);

    __shared__ float As[8][128];
    __shared__ float Bsh[8][128];

    int tid  = threadIdx.x;
    int brow = blockIdx.y * 128;

    int arow  = tid >> 1;         // 0..127
    int acol4 = (tid & 1) * 4;    // 0 or 4
    int browk = tid >> 5;         // 0..7
    int bcol4 = (tid & 31) * 4;   // 0..124

    int ty = tid >> 4, tx = tid & 15;

    float acc[8][8];
#pragma unroll
    for (int i = 0; i < 8; i++)
#pragma unroll
        for (int j = 0; j < 8; j++) acc[i][j] = 0.0f;

    for (int k0 = 0; k0 < K; k0 += 8) {
        float4 av = make_float4(0.f, 0.f, 0.f, 0.f);
        int gr = brow + arow;
        if (gr < M) av = *(const float4*)(A + (size_t)gr * K + k0 + acol4);
        As[acol4 + 0][arow] = av.x;
        As[acol4 + 1][arow] = av.y;
        As[acol4 + 2][arow] = av.z;
        As[acol4 + 3][arow] = av.w;

        float4 bv = make_float4(0.f, 0.f, 0.f, 0.f);
        if (bcol4 < N) bv = *(const float4*)(B + (size_t)(k0 + browk) * N + bcol4);
        *(float4*)(&Bsh[browk][bcol4]) = bv;
        __syncthreads();

#pragma unroll
        for (int k = 0; k < 8; k++) {
            float4 a0 = *(const float4*)(&As[k][ty * 8]);
            float4 a1 = *(const float4*)(&As[k][ty * 8 + 4]);
            float4 b0 = *(const float4*)(&Bsh[k][tx * 8]);
            float4 b1 = *(const float4*)(&Bsh[k][tx * 8 + 4]);
            float ra[8] = {a0.x, a0.y, a0.z, a0.w, a1.x, a1.y, a1.z, a1.w};
            float rb[8] = {b0.x, b0.y, b0.z, b0.w, b1.x, b1.y, b1.z, b1.w};
#pragma unroll
            for (int i = 0; i < 8; i++)
#pragma unroll
                for (int j = 0; j < 8; j++) acc[i][j] += ra[i] * rb[j];
        }
        __syncthreads();
    }

    int c0 = tx * 8;
    if (c0 >= N) return;   // N is 64 or 128, multiple of 8
    float bb[8];
#pragma unroll
    for (int j = 0; j < 8; j++) bb[j] = use_bias ? bias[c0 + j] : 0.0f;

#pragma unroll
    for (int i = 0; i < 8; i++) {
        int r = brow + ty * 8 + i;
        if (r >= M) continue;
        float4 o0 = make_float4(acc[i][0] + bb[0], acc[i][1] + bb[1],
                                acc[i][2] + bb[2], acc[i][3] + bb[3]);
        float4 o1 = make_float4(acc[i][4] + bb[4], acc[i][5] + bb[5],
                                acc[i][6] + bb[6], acc[i][7] + bb[7]);
        *(float4*)(C + (size_t)r * N + c0)     = o0;
        *(float4*)(C + (size_t)r * N + c0 + 4) = o1;
    }
}

// ---------------- aggregation: one warp per node ----------------
// g_h[v] = relu(g_selfp[v] + g_invdeg[v] * sum_{u in N(v)} g_tmp[u]), dim 128
__global__ __launch_bounds__(256) void k_agg_relu128() {
    int w = (blockIdx.x * blockDim.x + threadIdx.x) >> 5;
    int lane = threadIdx.x & 31;
    if (w >= NN) return;
    int beg = g_rowoff[w], end = g_rowoff[w + 1];
    float4 acc0 = make_float4(0.f, 0.f, 0.f, 0.f);
    float4 acc1 = make_float4(0.f, 0.f, 0.f, 0.f);
    int i = beg;
    for (; i + 1 < end; i += 2) {
        int u0 = g_csr[i], u1 = g_csr[i + 1];
        float4 t0 = *(const float4*)(g_tmp + (size_t)u0 * 128 + lane * 4);
        float4 t1 = *(const float4*)(g_tmp + (size_t)u1 * 128 + lane * 4);
        acc0.x += t0.x; acc0.y += t0.y; acc0.z += t0.z; acc0.w += t0.w;
        acc1.x += t1.x; acc1.y += t1.y; acc1.z += t1.z; acc1.w += t1.w;
    }
    if (i < end) {
        int u0 = g_csr[i];
        float4 t0 = *(const float4*)(g_tmp + (size_t)u0 * 128 + lane * 4);
        acc0.x += t0.x; acc0.y += t0.y; acc0.z += t0.z; acc0.w += t0.w;
    }
    float s = g_invdeg[w];
    float4 sp = *(const float4*)(g_selfp + (size_t)w * 128 + lane * 4);
    float4 o;
    o.x = fmaxf(fmaf(acc0.x + acc1.x, s, sp.x), 0.f);
    o.y = fmaxf(fmaf(acc0.y + acc1.y, s, sp.y), 0.f);
    o.z = fmaxf(fmaf(acc0.z + acc1.z, s, sp.z), 0.f);
    o.w = fmaxf(fmaf(acc0.w + acc1.w, s, sp.w), 0.f);
    *(float4*)(g_h + (size_t)w * 128 + lane * 4) = o;
}

// final layer: dim 64, fused log_softmax, warp-local (2 logits/lane)
__global__ __launch_bounds__(256) void k_agg_lsm64(float* __restrict__ out) {
    int w = (blockIdx.x * blockDim.x + threadIdx.x) >> 5;
    int lane = threadIdx.x & 31;
    if (w >= NN) return;
    int beg = g_rowoff[w], end = g_rowoff[w + 1];
    float2 acc0 = make_float2(0.f, 0.f);
    float2 acc1 = make_float2(0.f, 0.f);
    int i = beg;
    for (; i + 1 < end; i += 2) {
        int u0 = g_csr[i], u1 = g_csr[i + 1];
        float2 t0 = *(const float2*)(g_tmp + (size_t)u0 * 64 + lane * 2);
        float2 t1 = *(const float2*)(g_tmp + (size_t)u1 * 64 + lane * 2);
        acc0.x += t0.x; acc0.y += t0.y;
        acc1.x += t1.x; acc1.y += t1.y;
    }
    if (i < end) {
        int u0 = g_csr[i];
        float2 t0 = *(const float2*)(g_tmp + (size_t)u0 * 64 + lane * 2);
        acc0.x += t0.x; acc0.y += t0.y;
    }
    float s = g_invdeg[w];
    float2 sp = *(const float2*)(g_selfp + (size_t)w * 64 + lane * 2);
    float v0 = fmaf(acc0.x + acc1.x, s, sp.x);
    float v1 = fmaf(acc0.y + acc1.y, s, sp.y);
    float m = fmaxf(v0, v1);
#pragma unroll
    for (int o = 16; o; o >>= 1) m = fmaxf(m, __shfl_xor_sync(0xffffffffu, m, o));
    float e = expf(v0 - m) + expf(v1 - m);
#pragma unroll
    for (int o = 16; o; o >>= 1) e += __shfl_xor_sync(0xffffffffu, e, o);
    float lse = m + logf(e);
    float2 res = make_float2(v0 - lse, v1 - lse);
    *(float2*)(out + (size_t)w * 64 + lane * 2) = res;
}

// ---------------- launch: pure kernel launches, zero other API calls ----------------
extern "C" void kernel_launch(void* const* d_in, const int* in_sizes, int n_in,
                              void* d_out, int out_size) {
    const float* x   = (const float*)d_in[0];
    const int*   src = (const int*)d_in[1];
    const int*   dst = (const int*)d_in[2];
    const float* Ws0 = (const float*)d_in[3];
    const float* Wn0 = (const float*)d_in[4];
    const float* b0  = (const float*)d_in[5];
    const float* Ws1 = (const float*)d_in[6];
    const float* Wn1 = (const float*)d_in[7];
    const float* b1  = (const float*)d_in[8];
    const float* Ws2 = (const float*)d_in[9];
    const float* Wn2 = (const float*)d_in[10];
    const float* b2  = (const float*)d_in[11];
    float* out = (float*)d_out;

    // --- build CSR by dst (reused by all 3 layers) ---
    k_zero_deg<<<(NN + 255) / 256, 256>>>();
    k_hist<<<(NE + 255) / 256, 256>>>(dst);
    k_scan_partial<<<NBLK_SCAN, 256>>>();
    k_scan_bsums<<<1, 32>>>();
    k_scan_final<<<NBLK_SCAN, 256>>>();
    k_scatter<<<(NE + 255) / 256, 256>>>(src, dst);

    dim3 ggemm(2, (NN + 127) / 128);
    dim3 gagg((NN + 7) / 8, 1);

    // layer 0: x -> g_h (relu)     [A = x param]
    k_gemm_dual<0><<<ggemm, 256>>>(x, Ws0, Wn0, b0, 128);
    k_agg_relu128<<<gagg, 256>>>();

    // layer 1: g_h -> g_h (relu)   [A = g_h]
    k_gemm_dual<1><<<ggemm, 256>>>(nullptr, Ws1, Wn1, b1, 128);
    k_agg_relu128<<<gagg, 256>>>();

    // layer 2: g_h -> out (dim 64, agg after projection, fused log_softmax)
    k_gemm_dual<1><<<ggemm, 256>>>(nullptr, Ws2, Wn2, b2, 64);
    k_agg_lsm64<<<gagg, 256>>>(out);
}

// round 8
// speedup vs baseline: 1.6488x; 1.6488x over previous
#include <cuda_runtime.h>
#include <cuda_bf16.h>
#include <cstdint>
#include <cmath>

#define NN 100000
#define NE 1600000
#define NT 782                 // ceil(NN/128)
#define NPAD (NT * 128)        // 100096
#define NBLK_SCAN ((NN + 1023) / 1024)   // 98

// ---------------- static device scratch ----------------
__device__ int   g_deg[NN];
__device__ int   g_rowoff[NN + 1];
__device__ int   g_cursor[NN];
__device__ int   g_csr[NE];
__device__ int   g_bsum[128];
__device__ float g_invdeg[NN];
__device__ float g_selfp[(size_t)NN * 128];
__device__ float g_tmp[(size_t)NN * 128];
__device__ __nv_bfloat16 g_ahi[(size_t)NPAD * 128];   // activations hi (x, then h)
__device__ __nv_bfloat16 g_alo[(size_t)NPAD * 128];   // activations lo
__device__ __nv_bfloat16 g_bhi[3 * 256 * 128];        // weights [n][k] hi, per layer
__device__ __nv_bfloat16 g_blo[3 * 256 * 128];        // weights lo

// ---------------- CSR preprocessing ----------------
__global__ void k_zero_deg() {
    int i = blockIdx.x * blockDim.x + threadIdx.x;
    if (i < NN) g_deg[i] = 0;
}
__global__ void k_hist(const int* __restrict__ dst) {
    int e = blockIdx.x * blockDim.x + threadIdx.x;
    if (e < NE) atomicAdd(&g_deg[dst[e]], 1);
}
__global__ void k_scan_partial() {
    __shared__ int wsum[8];
    int t = threadIdx.x;
    int base = blockIdx.x * 1024 + t * 4;
    int s = 0;
#pragma unroll
    for (int i = 0; i < 4; i++) { int idx = base + i; if (idx < NN) s += g_deg[idx]; }
#pragma unroll
    for (int o = 16; o; o >>= 1) s += __shfl_xor_sync(0xffffffffu, s, o);
    if ((t & 31) == 0) wsum[t >> 5] = s;
    __syncthreads();
    if (t == 0) {
        int tot = 0;
#pragma unroll
        for (int i = 0; i < 8; i++) tot += wsum[i];
        g_bsum[blockIdx.x] = tot;
    }
}
__global__ void k_scan_bsums() {
    __shared__ int ws[4];
    int t = threadIdx.x, lane = t & 31, wid = t >> 5;
    int v = (t < NBLK_SCAN) ? g_bsum[t] : 0;
    int inc = v;
#pragma unroll
    for (int o = 1; o < 32; o <<= 1) {
        int y = __shfl_up_sync(0xffffffffu, inc, o);
        if (lane >= o) inc += y;
    }
    if (lane == 31) ws[wid] = inc;
    __syncthreads();
    if (t == 0) {
        int acc = 0;
#pragma unroll
        for (int i = 0; i < 4; i++) { int x = ws[i]; ws[i] = acc; acc += x; }
    }
    __syncthreads();
    if (t < NBLK_SCAN) g_bsum[t] = ws[wid] + inc - v;
}
__global__ void k_scan_final() {
    __shared__ int wsum[8];
    int t = threadIdx.x;
    int base = blockIdx.x * 1024 + t * 4;
    int v[4];
    int s = 0;
#pragma unroll
    for (int i = 0; i < 4; i++) {
        int idx = base + i;
        v[i] = (idx < NN) ? g_deg[idx] : 0;
        s += v[i];
    }
    int lane = t & 31, wid = t >> 5;
    int inc = s;
#pragma unroll
    for (int o = 1; o < 32; o <<= 1) {
        int y = __shfl_up_sync(0xffffffffu, inc, o);
        if (lane >= o) inc += y;
    }
    if (lane == 31) wsum[wid] = inc;
    __syncthreads();
    if (t == 0) {
        int acc = 0;
#pragma unroll
        for (int i = 0; i < 8; i++) { int x = wsum[i]; wsum[i] = acc; acc += x; }
    }
    __syncthreads();
    int excl = g_bsum[blockIdx.x] + wsum[wid] + (inc - s);
#pragma unroll
    for (int i = 0; i < 4; i++) {
        int idx = base + i;
        if (idx < NN) {
            g_rowoff[idx] = excl;
            g_cursor[idx] = excl;
            g_invdeg[idx] = 1.0f / fmaxf((float)v[i], 1.0f);
            excl += v[i];
        }
    }
    if (blockIdx.x == 0 && t == 0) g_rowoff[NN] = NE;
}
__global__ void k_scatter(const int* __restrict__ src, const int* __restrict__ dst) {
    int e = blockIdx.x * blockDim.x + threadIdx.x;
    if (e < NE) {
        int p = atomicAdd(&g_cursor[dst[e]], 1);
        g_csr[p] = src[e];
    }
}

// ---------------- fp32 -> bf16 hi/lo ----------------
__device__ __forceinline__ uint32_t pack_bf(__nv_bfloat16 a, __nv_bfloat16 b) {
    return (uint32_t)__bfloat16_as_ushort(a) | ((uint32_t)__bfloat16_as_ushort(b) << 16);
}
__device__ __forceinline__ void split4(float4 v, uint2& hi, uint2& lo) {
    __nv_bfloat16 h0 = __float2bfloat16(v.x), h1 = __float2bfloat16(v.y);
    __nv_bfloat16 h2 = __float2bfloat16(v.z), h3 = __float2bfloat16(v.w);
    __nv_bfloat16 l0 = __float2bfloat16(v.x - __bfloat162float(h0));
    __nv_bfloat16 l1 = __float2bfloat16(v.y - __bfloat162float(h1));
    __nv_bfloat16 l2 = __float2bfloat16(v.z - __bfloat162float(h2));
    __nv_bfloat16 l3 = __float2bfloat16(v.w - __bfloat162float(h3));
    hi.x = pack_bf(h0, h1); hi.y = pack_bf(h2, h3);
    lo.x = pack_bf(l0, l1); lo.y = pack_bf(l2, l3);
}
__global__ void k_convert_x(const float* __restrict__ x) {
    size_t i = (size_t)(blockIdx.x * blockDim.x + threadIdx.x) * 4;
    if (i >= (size_t)NN * 128) return;
    float4 v = *(const float4*)(x + i);
    uint2 hi, lo;
    split4(v, hi, lo);
    *(uint2*)(g_ahi + i) = hi;
    *(uint2*)(g_alo + i) = lo;
}
template <int NO1>
__global__ void k_convert_w(const float* __restrict__ Ws, const float* __restrict__ Wn, int layer) {
    const int NO = 2 * NO1;
    int idx = blockIdx.x * blockDim.x + threadIdx.x;   // n*128 + k
    if (idx >= NO * 128) return;
    int n = idx >> 7, k = idx & 127;
    float v = (n < NO1) ? Ws[k * NO1 + n] : Wn[k * NO1 + (n - NO1)];
    __nv_bfloat16 h = __float2bfloat16(v);
    __nv_bfloat16 l = __float2bfloat16(v - __bfloat162float(h));
    g_bhi[layer * 32768 + idx] = h;
    g_blo[layer * 32768 + idx] = l;
}

// ---------------- mma.sync helpers ----------------
__device__ __forceinline__ uint32_t smem_u32(const void* p) {
    uint32_t a;
    asm("{ .reg .u64 t; cvta.to.shared.u64 t, %1; cvt.u32.u64 %0, t; }" : "=r"(a) : "l"(p));
    return a;
}
__device__ __forceinline__ void ldm_x4(uint32_t& d0, uint32_t& d1, uint32_t& d2, uint32_t& d3,
                                       uint32_t addr) {
    asm volatile("ldmatrix.sync.aligned.m8n8.x4.shared.b16 {%0,%1,%2,%3}, [%4];"
        : "=r"(d0), "=r"(d1), "=r"(d2), "=r"(d3) : "r"(addr));
}
__device__ __forceinline__ void mma_bf16(float* c, const uint32_t* a, uint32_t b0, uint32_t b1) {
    asm volatile("mma.sync.aligned.m16n8k16.row.col.f32.bf16.bf16.f32 "
        "{%0,%1,%2,%3}, {%4,%5,%6,%7}, {%8,%9}, {%0,%1,%2,%3};"
        : "+f"(c[0]), "+f"(c[1]), "+f"(c[2]), "+f"(c[3])
        : "r"(a[0]), "r"(a[1]), "r"(a[2]), "r"(a[3]), "r"(b0), "r"(b1));
}

// ---------------- mma GEMM (48KB STATIC shared -> no attribute API needed) ----------
// CTA computes D[128,64] = A_tile[128,128] @ B_strip[64,128]^T via the 3-term
// bf16 split (Ahi*Bhi + Ahi*Blo + Alo*Bhi), K staged in two 64-halves.
// Global col gc = blockIdx.x*64 + local; gc < NO1 -> g_selfp(+bias), else g_tmp.
// SMEM rows are 64 bf16 = 128 B = 8 x 16B chunks; chunk c of row r at
// r*128 + ((c ^ (r&7))*16) (XOR swizzle, conflict-free ldmatrix).
__global__ __launch_bounds__(256) void k_gemm_mma(int layer, int NO1,
                                                  const float* __restrict__ bias) {
    constexpr int A_HI = 0, A_LO = 16384, B_HI = 32768, B_LO = 40960;
    __shared__ __align__(16) char smem[49152];
    uint32_t sb = smem_u32(smem);
    int tid = threadIdx.x, wid = tid >> 5, lane = tid & 31;
    int tile = blockIdx.y;
    int bn0 = blockIdx.x * 64;

    const __nv_bfloat16* ah = g_ahi + (size_t)tile * 16384;
    const __nv_bfloat16* al = g_alo + (size_t)tile * 16384;
    const __nv_bfloat16* bh = g_bhi + layer * 32768 + (size_t)bn0 * 128;
    const __nv_bfloat16* bl = g_blo + layer * 32768 + (size_t)bn0 * 128;

    int wm = (wid & 3) * 32;    // warp m base (4 warps over 128 rows)
    int wn = (wid >> 2) * 32;   // warp n base (2 warps over 64 cols)
    int lrow = lane & 15, lchunk = lane >> 4;

    float acc[2][4][4];
#pragma unroll
    for (int i = 0; i < 2; i++)
#pragma unroll
        for (int j = 0; j < 4; j++)
#pragma unroll
            for (int q = 0; q < 4; q++) acc[i][j][q] = 0.0f;

#pragma unroll
    for (int ks0 = 0; ks0 < 2; ks0++) {          // K stage: columns [64*ks0, 64*ks0+64)
        if (ks0) __syncthreads();                // protect smem reuse
        // A: 128 rows x 8 chunks, hi+lo
        for (int i = tid; i < 1024; i += 256) {
            int r = i >> 3, c = i & 7;
            uint32_t off = (uint32_t)r * 128u + (uint32_t)((c ^ (r & 7)) << 4);
            *(uint4*)(smem + A_HI + off) = *(const uint4*)(ah + r * 128 + ks0 * 64 + c * 8);
            *(uint4*)(smem + A_LO + off) = *(const uint4*)(al + r * 128 + ks0 * 64 + c * 8);
        }
        // B: 64 n-rows x 8 chunks, hi+lo
        for (int i = tid; i < 512; i += 256) {
            int r = i >> 3, c = i & 7;
            uint32_t off = (uint32_t)r * 128u + (uint32_t)((c ^ (r & 7)) << 4);
            *(uint4*)(smem + B_HI + off) = *(const uint4*)(bh + r * 128 + ks0 * 64 + c * 8);
            *(uint4*)(smem + B_LO + off) = *(const uint4*)(bl + r * 128 + ks0 * 64 + c * 8);
        }
        __syncthreads();

#pragma unroll
        for (int ks = 0; ks < 4; ks++) {         // 4 k-steps of 16 within the stage
            int c0 = 2 * ks;
            uint32_t ahi[2][4], alo[2][4];
#pragma unroll
            for (int mt = 0; mt < 2; mt++) {
                int r = wm + mt * 16 + lrow;
                uint32_t off = (uint32_t)r * 128u + (uint32_t)((((c0 + lchunk) ^ (r & 7))) << 4);
                ldm_x4(ahi[mt][0], ahi[mt][1], ahi[mt][2], ahi[mt][3], sb + A_HI + off);
                ldm_x4(alo[mt][0], alo[mt][1], alo[mt][2], alo[mt][3], sb + A_LO + off);
            }
            uint32_t bhi[4][2], blo[4][2];
#pragma unroll
            for (int nq = 0; nq < 2; nq++) {     // each x4 covers n-tiles 2nq, 2nq+1
                int r = wn + nq * 16 + lrow;
                uint32_t off = (uint32_t)r * 128u + (uint32_t)((((c0 + lchunk) ^ (r & 7))) << 4);
                uint32_t t0, t1, t2, t3;
                ldm_x4(t0, t1, t2, t3, sb + B_HI + off);
                bhi[2 * nq][0] = t0; bhi[2 * nq][1] = t2;
                bhi[2 * nq + 1][0] = t1; bhi[2 * nq + 1][1] = t3;
                ldm_x4(t0, t1, t2, t3, sb + B_LO + off);
                blo[2 * nq][0] = t0; blo[2 * nq][1] = t2;
                blo[2 * nq + 1][0] = t1; blo[2 * nq + 1][1] = t3;
            }
#pragma unroll
            for (int mt = 0; mt < 2; mt++)
#pragma unroll
                for (int nt = 0; nt < 4; nt++) {
                    mma_bf16(acc[mt][nt], ahi[mt], bhi[nt][0], bhi[nt][1]);
                    mma_bf16(acc[mt][nt], ahi[mt], blo[nt][0], blo[nt][1]);
                    mma_bf16(acc[mt][nt], alo[mt], bhi[nt][0], bhi[nt][1]);
                }
        }
    }

    // epilogue: c0,c1 -> row qrow cols (qcol,qcol+1); c2,c3 -> row qrow+8
    int qrow = lane >> 2;
    int qcol = (lane & 3) * 2;
#pragma unroll
    for (int mt = 0; mt < 2; mt++) {
#pragma unroll
        for (int nt = 0; nt < 4; nt++) {
            int r0 = tile * 128 + wm + mt * 16 + qrow;
            int gc = bn0 + wn + nt * 8 + qcol;
            float2 v0 = make_float2(acc[mt][nt][0], acc[mt][nt][1]);
            float2 v1 = make_float2(acc[mt][nt][2], acc[mt][nt][3]);
            if (gc < NO1) {
                float2 bv = *(const float2*)(bias + gc);
                v0.x += bv.x; v0.y += bv.y;
                v1.x += bv.x; v1.y += bv.y;
                if (r0 < NN)     *(float2*)(g_selfp + (size_t)r0 * NO1 + gc) = v0;
                if (r0 + 8 < NN) *(float2*)(g_selfp + (size_t)(r0 + 8) * NO1 + gc) = v1;
            } else {
                int tc = gc - NO1;
                if (r0 < NN)     *(float2*)(g_tmp + (size_t)r0 * NO1 + tc) = v0;
                if (r0 + 8 < NN) *(float2*)(g_tmp + (size_t)(r0 + 8) * NO1 + tc) = v1;
            }
        }
    }
}

// ---------------- aggregation ----------------
// h = relu(selfp + invdeg * sum tmp[nbr]), dim 128; writes bf16 hi/lo for next layer
__global__ __launch_bounds__(256) void k_agg_relu128() {
    int w = (blockIdx.x * blockDim.x + threadIdx.x) >> 5;
    int lane = threadIdx.x & 31;
    if (w >= NN) return;
    int beg = g_rowoff[w], end = g_rowoff[w + 1];
    float4 acc0 = make_float4(0.f, 0.f, 0.f, 0.f);
    float4 acc1 = make_float4(0.f, 0.f, 0.f, 0.f);
    int i = beg;
    for (; i + 1 < end; i += 2) {
        int u0 = g_csr[i], u1 = g_csr[i + 1];
        float4 t0 = *(const float4*)(g_tmp + (size_t)u0 * 128 + lane * 4);
        float4 t1 = *(const float4*)(g_tmp + (size_t)u1 * 128 + lane * 4);
        acc0.x += t0.x; acc0.y += t0.y; acc0.z += t0.z; acc0.w += t0.w;
        acc1.x += t1.x; acc1.y += t1.y; acc1.z += t1.z; acc1.w += t1.w;
    }
    if (i < end) {
        int u0 = g_csr[i];
        float4 t0 = *(const float4*)(g_tmp + (size_t)u0 * 128 + lane * 4);
        acc0.x += t0.x; acc0.y += t0.y; acc0.z += t0.z; acc0.w += t0.w;
    }
    float s = g_invdeg[w];
    float4 sp = *(const float4*)(g_selfp + (size_t)w * 128 + lane * 4);
    float4 o;
    o.x = fmaxf(fmaf(acc0.x + acc1.x, s, sp.x), 0.f);
    o.y = fmaxf(fmaf(acc0.y + acc1.y, s, sp.y), 0.f);
    o.z = fmaxf(fmaf(acc0.z + acc1.z, s, sp.z), 0.f);
    o.w = fmaxf(fmaf(acc0.w + acc1.w, s, sp.w), 0.f);
    uint2 hi, lo;
    split4(o, hi, lo);
    *(uint2*)(g_ahi + (size_t)w * 128 + lane * 4) = hi;
    *(uint2*)(g_alo + (size_t)w * 128 + lane * 4) = lo;
}

// final layer: dim 64, fused log_softmax
__global__ __launch_bounds__(256) void k_agg_lsm64(float* __restrict__ out) {
    int w = (blockIdx.x * blockDim.x + threadIdx.x) >> 5;
    int lane = threadIdx.x & 31;
    if (w >= NN) return;
    int beg = g_rowoff[w], end = g_rowoff[w + 1];
    float2 acc0 = make_float2(0.f, 0.f);
    float2 acc1 = make_float2(0.f, 0.f);
    int i = beg;
    for (; i + 1 < end; i += 2) {
        int u0 = g_csr[i], u1 = g_csr[i + 1];
        float2 t0 = *(const float2*)(g_tmp + (size_t)u0 * 64 + lane * 2);
        float2 t1 = *(const float2*)(g_tmp + (size_t)u1 * 64 + lane * 2);
        acc0.x += t0.x; acc0.y += t0.y;
        acc1.x += t1.x; acc1.y += t1.y;
    }
    if (i < end) {
        int u0 = g_csr[i];
        float2 t0 = *(const float2*)(g_tmp + (size_t)u0 * 64 + lane * 2);
        acc0.x += t0.x; acc0.y += t0.y;
    }
    float s = g_invdeg[w];
    float2 sp = *(const float2*)(g_selfp + (size_t)w * 64 + lane * 2);
    float v0 = fmaf(acc0.x + acc1.x, s, sp.x);
    float v1 = fmaf(acc0.y + acc1.y, s, sp.y);
    float m = fmaxf(v0, v1);
#pragma unroll
    for (int o = 16; o; o >>= 1) m = fmaxf(m, __shfl_xor_sync(0xffffffffu, m, o));
    float e = expf(v0 - m) + expf(v1 - m);
#pragma unroll
    for (int o = 16; o; o >>= 1) e += __shfl_xor_sync(0xffffffffu, e, o);
    float lse = m + logf(e);
    float2 res = make_float2(v0 - lse, v1 - lse);
    *(float2*)(out + (size_t)w * 64 + lane * 2) = res;
}

// ---------------- launch: PURE kernel launches, zero other host API ----------------
extern "C" void kernel_launch(void* const* d_in, const int* in_sizes, int n_in,
                              void* d_out, int out_size) {
    const float* x   = (const float*)d_in[0];
    const int*   src = (const int*)d_in[1];
    const int*   dst = (const int*)d_in[2];
    const float* Ws0 = (const float*)d_in[3];
    const float* Wn0 = (const float*)d_in[4];
    const float* b0  = (const float*)d_in[5];
    const float* Ws1 = (const float*)d_in[6];
    const float* Wn1 = (const float*)d_in[7];
    const float* b1  = (const float*)d_in[8];
    const float* Ws2 = (const float*)d_in[9];
    const float* Wn2 = (const float*)d_in[10];
    const float* b2  = (const float*)d_in[11];
    float* out = (float*)d_out;

    // --- CSR build ---
    k_zero_deg<<<(NN + 255) / 256, 256>>>();
    k_hist<<<(NE + 255) / 256, 256>>>(dst);
    k_scan_partial<<<NBLK_SCAN, 256>>>();
    k_scan_bsums<<<1, 128>>>();
    k_scan_final<<<NBLK_SCAN, 256>>>();
    k_scatter<<<(NE + 255) / 256, 256>>>(src, dst);

    // --- conversions ---
    k_convert_x<<<(NN * 128 / 4 + 255) / 256, 256>>>(x);
    k_convert_w<128><<<(256 * 128 + 255) / 256, 256>>>(Ws0, Wn0, 0);
    k_convert_w<128><<<(256 * 128 + 255) / 256, 256>>>(Ws1, Wn1, 1);
    k_convert_w<64><<<(128 * 128 + 255) / 256, 256>>>(Ws2, Wn2, 2);

    dim3 gagg((NN + 7) / 8, 1);
    dim3 gg2(4, NT);   // layers 0/1: N=256 -> 4 column strips of 64
    dim3 gg1(2, NT);   // layer 2:    N=128 -> 2

    // layer 0
    k_gemm_mma<<<gg2, 256>>>(0, 128, b0);
    k_agg_relu128<<<gagg, 256>>>();
    // layer 1
    k_gemm_mma<<<gg2, 256>>>(1, 128, b1);
    k_agg_relu128<<<gagg, 256>>>();
    // layer 2 (dim 64, agg after projection, fused log_softmax)
    k_gemm_mma<<<gg1, 256>>>(2, 64, b2);
    k_agg_lsm64<<<gagg, 256>>>(out);
}

// round 9
// speedup vs baseline: 1.7588x; 1.0667x over previous
#include <cuda_runtime.h>
#include <cuda_bf16.h>
#include <cuda_fp16.h>
#include <cstdint>
#include <cmath>

#define NN 100000
#define NE 1600000
#define NT 782                 // ceil(NN/128)
#define NPAD (NT * 128)        // 100096
#define NBLK_SCAN ((NN + 1023) / 1024)   // 98

// ---------------- static device scratch ----------------
__device__ int   g_deg[NN];
__device__ int   g_rowoff[NN + 1];
__device__ int   g_cursor[NN];
__device__ int   g_csr[NE];
__device__ int   g_bsum[128];
__device__ float g_invdeg[NN];
__device__ float g_selfp[(size_t)NN * 128];
__device__ __half g_tmph[(size_t)NN * 128];           // neighbor projection, fp16
__device__ __nv_bfloat16 g_ahi[(size_t)NPAD * 128];   // activations hi (x, then h)
__device__ __nv_bfloat16 g_alo[(size_t)NPAD * 128];   // activations lo
__device__ __nv_bfloat16 g_bhi[3 * 256 * 128];        // weights [n][k] hi, per layer
__device__ __nv_bfloat16 g_blo[3 * 256 * 128];        // weights lo

// ---------------- CSR preprocessing ----------------
__global__ void k_zero_deg() {
    int i = blockIdx.x * blockDim.x + threadIdx.x;
    if (i < NN) g_deg[i] = 0;
}
__global__ void k_hist(const int* __restrict__ dst) {
    int e4 = blockIdx.x * blockDim.x + threadIdx.x;
    if (e4 < NE / 4) {
        int4 d = ((const int4*)dst)[e4];
        atomicAdd(&g_deg[d.x], 1);
        atomicAdd(&g_deg[d.y], 1);
        atomicAdd(&g_deg[d.z], 1);
        atomicAdd(&g_deg[d.w], 1);
    }
}
__global__ void k_scan_partial() {
    __shared__ int wsum[8];
    int t = threadIdx.x;
    int base = blockIdx.x * 1024 + t * 4;
    int s = 0;
#pragma unroll
    for (int i = 0; i < 4; i++) { int idx = base + i; if (idx < NN) s += g_deg[idx]; }
#pragma unroll
    for (int o = 16; o; o >>= 1) s += __shfl_xor_sync(0xffffffffu, s, o);
    if ((t & 31) == 0) wsum[t >> 5] = s;
    __syncthreads();
    if (t == 0) {
        int tot = 0;
#pragma unroll
        for (int i = 0; i < 8; i++) tot += wsum[i];
        g_bsum[blockIdx.x] = tot;
    }
}
__global__ void k_scan_bsums() {
    __shared__ int ws[4];
    int t = threadIdx.x, lane = t & 31, wid = t >> 5;
    int v = (t < NBLK_SCAN) ? g_bsum[t] : 0;
    int inc = v;
#pragma unroll
    for (int o = 1; o < 32; o <<= 1) {
        int y = __shfl_up_sync(0xffffffffu, inc, o);
        if (lane >= o) inc += y;
    }
    if (lane == 31) ws[wid] = inc;
    __syncthreads();
    if (t == 0) {
        int acc = 0;
#pragma unroll
        for (int i = 0; i < 4; i++) { int x = ws[i]; ws[i] = acc; acc += x; }
    }
    __syncthreads();
    if (t < NBLK_SCAN) g_bsum[t] = ws[wid] + inc - v;
}
__global__ void k_scan_final() {
    __shared__ int wsum[8];
    int t = threadIdx.x;
    int base = blockIdx.x * 1024 + t * 4;
    int v[4];
    int s = 0;
#pragma unroll
    for (int i = 0; i < 4; i++) {
        int idx = base + i;
        v[i] = (idx < NN) ? g_deg[idx] : 0;
        s += v[i];
    }
    int lane = t & 31, wid = t >> 5;
    int inc = s;
#pragma unroll
    for (int o = 1; o < 32; o <<= 1) {
        int y = __shfl_up_sync(0xffffffffu, inc, o);
        if (lane >= o) inc += y;
    }
    if (lane == 31) wsum[wid] = inc;
    __syncthreads();
    if (t == 0) {
        int acc = 0;
#pragma unroll
        for (int i = 0; i < 8; i++) { int x = wsum[i]; wsum[i] = acc; acc += x; }
    }
    __syncthreads();
    int excl = g_bsum[blockIdx.x] + wsum[wid] + (inc - s);
#pragma unroll
    for (int i = 0; i < 4; i++) {
        int idx = base + i;
        if (idx < NN) {
            g_rowoff[idx] = excl;
            g_cursor[idx] = excl;
            g_invdeg[idx] = 1.0f / fmaxf((float)v[i], 1.0f);
            excl += v[i];
        }
    }
    if (blockIdx.x == 0 && t == 0) g_rowoff[NN] = NE;
}
__global__ void k_scatter(const int* __restrict__ src, const int* __restrict__ dst) {
    int e4 = blockIdx.x * blockDim.x + threadIdx.x;
    if (e4 < NE / 4) {
        int4 sv = ((const int4*)src)[e4];
        int4 dv = ((const int4*)dst)[e4];
        g_csr[atomicAdd(&g_cursor[dv.x], 1)] = sv.x;
        g_csr[atomicAdd(&g_cursor[dv.y], 1)] = sv.y;
        g_csr[atomicAdd(&g_cursor[dv.z], 1)] = sv.z;
        g_csr[atomicAdd(&g_cursor[dv.w], 1)] = sv.w;
    }
}

// ---------------- fp32 -> bf16 hi/lo ----------------
__device__ __forceinline__ uint32_t pack_bf(__nv_bfloat16 a, __nv_bfloat16 b) {
    return (uint32_t)__bfloat16_as_ushort(a) | ((uint32_t)__bfloat16_as_ushort(b) << 16);
}
__device__ __forceinline__ void split4(float4 v, uint2& hi, uint2& lo) {
    __nv_bfloat16 h0 = __float2bfloat16(v.x), h1 = __float2bfloat16(v.y);
    __nv_bfloat16 h2 = __float2bfloat16(v.z), h3 = __float2bfloat16(v.w);
    __nv_bfloat16 l0 = __float2bfloat16(v.x - __bfloat162float(h0));
    __nv_bfloat16 l1 = __float2bfloat16(v.y - __bfloat162float(h1));
    __nv_bfloat16 l2 = __float2bfloat16(v.z - __bfloat162float(h2));
    __nv_bfloat16 l3 = __float2bfloat16(v.w - __bfloat162float(h3));
    hi.x = pack_bf(h0, h1); hi.y = pack_bf(h2, h3);
    lo.x = pack_bf(l0, l1); lo.y = pack_bf(l2, l3);
}
__global__ void k_convert_x(const float* __restrict__ x) {
    size_t i = (size_t)(blockIdx.x * blockDim.x + threadIdx.x) * 4;
    if (i >= (size_t)NN * 128) return;
    float4 v = *(const float4*)(x + i);
    uint2 hi, lo;
    split4(v, hi, lo);
    *(uint2*)(g_ahi + i) = hi;
    *(uint2*)(g_alo + i) = lo;
}
template <int NO1>
__global__ void k_convert_w(const float* __restrict__ Ws, const float* __restrict__ Wn, int layer) {
    const int NO = 2 * NO1;
    int idx = blockIdx.x * blockDim.x + threadIdx.x;   // n*128 + k
    if (idx >= NO * 128) return;
    int n = idx >> 7, k = idx & 127;
    float v = (n < NO1) ? Ws[k * NO1 + n] : Wn[k * NO1 + (n - NO1)];
    __nv_bfloat16 h = __float2bfloat16(v);
    __nv_bfloat16 l = __float2bfloat16(v - __bfloat162float(h));
    g_bhi[layer * 32768 + idx] = h;
    g_blo[layer * 32768 + idx] = l;
}

// ---------------- mma.sync helpers ----------------
__device__ __forceinline__ uint32_t smem_u32(const void* p) {
    uint32_t a;
    asm("{ .reg .u64 t; cvta.to.shared.u64 t, %1; cvt.u32.u64 %0, t; }" : "=r"(a) : "l"(p));
    return a;
}
__device__ __forceinline__ void ldm_x4(uint32_t& d0, uint32_t& d1, uint32_t& d2, uint32_t& d3,
                                       uint32_t addr) {
    asm volatile("ldmatrix.sync.aligned.m8n8.x4.shared.b16 {%0,%1,%2,%3}, [%4];"
        : "=r"(d0), "=r"(d1), "=r"(d2), "=r"(d3) : "r"(addr));
}
__device__ __forceinline__ void mma_bf16(float* c, const uint32_t* a, uint32_t b0, uint32_t b1) {
    asm volatile("mma.sync.aligned.m16n8k16.row.col.f32.bf16.bf16.f32 "
        "{%0,%1,%2,%3}, {%4,%5,%6,%7}, {%8,%9}, {%0,%1,%2,%3};"
        : "+f"(c[0]), "+f"(c[1]), "+f"(c[2]), "+f"(c[3])
        : "r"(a[0]), "r"(a[1]), "r"(a[2]), "r"(a[3]), "r"(b0), "r"(b1));
}

// ---------------- mma GEMM (48KB STATIC shared) ----------
// CTA computes D[128,64] = A_tile[128,128] @ B_strip[64,128]^T via the 3-term
// bf16 split (Ahi*Bhi + Ahi*Blo + Alo*Bhi), K staged in two 64-halves.
// Global col gc = blockIdx.x*64 + local; gc < NO1 -> g_selfp(+bias) fp32,
// else g_tmph fp16.
__global__ __launch_bounds__(256) void k_gemm_mma(int layer, int NO1,
                                                  const float* __restrict__ bias) {
    constexpr int A_HI = 0, A_LO = 16384, B_HI = 32768, B_LO = 40960;
    __shared__ __align__(16) char smem[49152];
    uint32_t sb = smem_u32(smem);
    int tid = threadIdx.x, wid = tid >> 5, lane = tid & 31;
    int tile = blockIdx.y;
    int bn0 = blockIdx.x * 64;

    const __nv_bfloat16* ah = g_ahi + (size_t)tile * 16384;
    const __nv_bfloat16* al = g_alo + (size_t)tile * 16384;
    const __nv_bfloat16* bh = g_bhi + layer * 32768 + (size_t)bn0 * 128;
    const __nv_bfloat16* bl = g_blo + layer * 32768 + (size_t)bn0 * 128;

    int wm = (wid & 3) * 32;    // warp m base (4 warps over 128 rows)
    int wn = (wid >> 2) * 32;   // warp n base (2 warps over 64 cols)
    int lrow = lane & 15, lchunk = lane >> 4;

    float acc[2][4][4];
#pragma unroll
    for (int i = 0; i < 2; i++)
#pragma unroll
        for (int j = 0; j < 4; j++)
#pragma unroll
            for (int q = 0; q < 4; q++) acc[i][j][q] = 0.0f;

#pragma unroll
    for (int ks0 = 0; ks0 < 2; ks0++) {          // K stage: columns [64*ks0, 64*ks0+64)
        if (ks0) __syncthreads();
        for (int i = tid; i < 1024; i += 256) {  // A: 128 rows x 8 chunks, hi+lo
            int r = i >> 3, c = i & 7;
            uint32_t off = (uint32_t)r * 128u + (uint32_t)((c ^ (r & 7)) << 4);
            *(uint4*)(smem + A_HI + off) = *(const uint4*)(ah + r * 128 + ks0 * 64 + c * 8);
            *(uint4*)(smem + A_LO + off) = *(const uint4*)(al + r * 128 + ks0 * 64 + c * 8);
        }
        for (int i = tid; i < 512; i += 256) {   // B: 64 n-rows x 8 chunks, hi+lo
            int r = i >> 3, c = i & 7;
            uint32_t off = (uint32_t)r * 128u + (uint32_t)((c ^ (r & 7)) << 4);
            *(uint4*)(smem + B_HI + off) = *(const uint4*)(bh + r * 128 + ks0 * 64 + c * 8);
            *(uint4*)(smem + B_LO + off) = *(const uint4*)(bl + r * 128 + ks0 * 64 + c * 8);
        }
        __syncthreads();

#pragma unroll
        for (int ks = 0; ks < 4; ks++) {         // 4 k-steps of 16 within the stage
            int c0 = 2 * ks;
            uint32_t ahi[2][4], alo[2][4];
#pragma unroll
            for (int mt = 0; mt < 2; mt++) {
                int r = wm + mt * 16 + lrow;
                uint32_t off = (uint32_t)r * 128u + (uint32_t)((((c0 + lchunk) ^ (r & 7))) << 4);
                ldm_x4(ahi[mt][0], ahi[mt][1], ahi[mt][2], ahi[mt][3], sb + A_HI + off);
                ldm_x4(alo[mt][0], alo[mt][1], alo[mt][2], alo[mt][3], sb + A_LO + off);
            }
            uint32_t bhi[4][2], blo[4][2];
#pragma unroll
            for (int nq = 0; nq < 2; nq++) {
                int r = wn + nq * 16 + lrow;
                uint32_t off = (uint32_t)r * 128u + (uint32_t)((((c0 + lchunk) ^ (r & 7))) << 4);
                uint32_t t0, t1, t2, t3;
                ldm_x4(t0, t1, t2, t3, sb + B_HI + off);
                bhi[2 * nq][0] = t0; bhi[2 * nq][1] = t2;
                bhi[2 * nq + 1][0] = t1; bhi[2 * nq + 1][1] = t3;
                ldm_x4(t0, t1, t2, t3, sb + B_LO + off);
                blo[2 * nq][0] = t0; blo[2 * nq][1] = t2;
                blo[2 * nq + 1][0] = t1; blo[2 * nq + 1][1] = t3;
            }
#pragma unroll
            for (int mt = 0; mt < 2; mt++)
#pragma unroll
                for (int nt = 0; nt < 4; nt++) {
                    mma_bf16(acc[mt][nt], ahi[mt], bhi[nt][0], bhi[nt][1]);
                    mma_bf16(acc[mt][nt], ahi[mt], blo[nt][0], blo[nt][1]);
                    mma_bf16(acc[mt][nt], alo[mt], bhi[nt][0], bhi[nt][1]);
                }
        }
    }

    // epilogue
    int qrow = lane >> 2;
    int qcol = (lane & 3) * 2;
#pragma unroll
    for (int mt = 0; mt < 2; mt++) {
#pragma unroll
        for (int nt = 0; nt < 4; nt++) {
            int r0 = tile * 128 + wm + mt * 16 + qrow;
            int gc = bn0 + wn + nt * 8 + qcol;
            float2 v0 = make_float2(acc[mt][nt][0], acc[mt][nt][1]);
            float2 v1 = make_float2(acc[mt][nt][2], acc[mt][nt][3]);
            if (gc < NO1) {
                float2 bv = *(const float2*)(bias + gc);
                v0.x += bv.x; v0.y += bv.y;
                v1.x += bv.x; v1.y += bv.y;
                if (r0 < NN)     *(float2*)(g_selfp + (size_t)r0 * NO1 + gc) = v0;
                if (r0 + 8 < NN) *(float2*)(g_selfp + (size_t)(r0 + 8) * NO1 + gc) = v1;
            } else {
                int tc = gc - NO1;
                if (r0 < NN)
                    *(__half2*)(g_tmph + (size_t)r0 * NO1 + tc) = __floats2half2_rn(v0.x, v0.y);
                if (r0 + 8 < NN)
                    *(__half2*)(g_tmph + (size_t)(r0 + 8) * NO1 + tc) = __floats2half2_rn(v1.x, v1.y);
            }
        }
    }
}

// ---------------- aggregation (fp16 gather, fp32 accumulate) ----------------
__device__ __forceinline__ void add_h4(float4& a, uint2 v) {
    __half2 p0 = *reinterpret_cast<__half2*>(&v.x);
    __half2 p1 = *reinterpret_cast<__half2*>(&v.y);
    float2 f0 = __half22float2(p0), f1 = __half22float2(p1);
    a.x += f0.x; a.y += f0.y; a.z += f1.x; a.w += f1.y;
}

// h = relu(selfp + invdeg * sum tmp[nbr]), dim 128; writes bf16 hi/lo for next layer
__global__ __launch_bounds__(256) void k_agg_relu128() {
    int w = (blockIdx.x * blockDim.x + threadIdx.x) >> 5;
    int lane = threadIdx.x & 31;
    if (w >= NN) return;
    int beg = g_rowoff[w], end = g_rowoff[w + 1];
    float4 acc0 = make_float4(0.f, 0.f, 0.f, 0.f);
    float4 acc1 = make_float4(0.f, 0.f, 0.f, 0.f);
    int i = beg;
    for (; i + 3 < end; i += 4) {
        int u0 = g_csr[i], u1 = g_csr[i + 1], u2 = g_csr[i + 2], u3 = g_csr[i + 3];
        uint2 v0 = *(const uint2*)(g_tmph + (size_t)u0 * 128 + lane * 4);
        uint2 v1 = *(const uint2*)(g_tmph + (size_t)u1 * 128 + lane * 4);
        uint2 v2 = *(const uint2*)(g_tmph + (size_t)u2 * 128 + lane * 4);
        uint2 v3 = *(const uint2*)(g_tmph + (size_t)u3 * 128 + lane * 4);
        add_h4(acc0, v0); add_h4(acc1, v1); add_h4(acc0, v2); add_h4(acc1, v3);
    }
    for (; i < end; i++) {
        int u0 = g_csr[i];
        uint2 v0 = *(const uint2*)(g_tmph + (size_t)u0 * 128 + lane * 4);
        add_h4(acc0, v0);
    }
    float s = g_invdeg[w];
    float4 sp = *(const float4*)(g_selfp + (size_t)w * 128 + lane * 4);
    float4 o;
    o.x = fmaxf(fmaf(acc0.x + acc1.x, s, sp.x), 0.f);
    o.y = fmaxf(fmaf(acc0.y + acc1.y, s, sp.y), 0.f);
    o.z = fmaxf(fmaf(acc0.z + acc1.z, s, sp.z), 0.f);
    o.w = fmaxf(fmaf(acc0.w + acc1.w, s, sp.w), 0.f);
    uint2 hi, lo;
    split4(o, hi, lo);
    *(uint2*)(g_ahi + (size_t)w * 128 + lane * 4) = hi;
    *(uint2*)(g_alo + (size_t)w * 128 + lane * 4) = lo;
}

// final layer: dim 64, fused log_softmax
__global__ __launch_bounds__(256) void k_agg_lsm64(float* __restrict__ out) {
    int w = (blockIdx.x * blockDim.x + threadIdx.x) >> 5;
    int lane = threadIdx.x & 31;
    if (w >= NN) return;
    int beg = g_rowoff[w], end = g_rowoff[w + 1];
    float2 acc0 = make_float2(0.f, 0.f);
    float2 acc1 = make_float2(0.f, 0.f);
    int i = beg;
    for (; i + 3 < end; i += 4) {
        int u0 = g_csr[i], u1 = g_csr[i + 1], u2 = g_csr[i + 2], u3 = g_csr[i + 3];
        float2 f0 = __half22float2(*(const __half2*)(g_tmph + (size_t)u0 * 64 + lane * 2));
        float2 f1 = __half22float2(*(const __half2*)(g_tmph + (size_t)u1 * 64 + lane * 2));
        float2 f2 = __half22float2(*(const __half2*)(g_tmph + (size_t)u2 * 64 + lane * 2));
        float2 f3 = __half22float2(*(const __half2*)(g_tmph + (size_t)u3 * 64 + lane * 2));
        acc0.x += f0.x + f2.x; acc0.y += f0.y + f2.y;
        acc1.x += f1.x + f3.x; acc1.y += f1.y + f3.y;
    }
    for (; i < end; i++) {
        int u0 = g_csr[i];
        float2 f0 = __half22float2(*(const __half2*)(g_tmph + (size_t)u0 * 64 + lane * 2));
        acc0.x += f0.x; acc0.y += f0.y;
    }
    float s = g_invdeg[w];
    float2 sp = *(const float2*)(g_selfp + (size_t)w * 64 + lane * 2);
    float v0 = fmaf(acc0.x + acc1.x, s, sp.x);
    float v1 = fmaf(acc0.y + acc1.y, s, sp.y);
    float m = fmaxf(v0, v1);
#pragma unroll
    for (int o = 16; o; o >>= 1) m = fmaxf(m, __shfl_xor_sync(0xffffffffu, m, o));
    float e = expf(v0 - m) + expf(v1 - m);
#pragma unroll
    for (int o = 16; o; o >>= 1) e += __shfl_xor_sync(0xffffffffu, e, o);
    float lse = m + logf(e);
    float2 res = make_float2(v0 - lse, v1 - lse);
    *(float2*)(out + (size_t)w * 64 + lane * 2) = res;
}

// ---------------- launch: PURE kernel launches, zero other host API ----------------
extern "C" void kernel_launch(void* const* d_in, const int* in_sizes, int n_in,
                              void* d_out, int out_size) {
    const float* x   = (const float*)d_in[0];
    const int*   src = (const int*)d_in[1];
    const int*   dst = (const int*)d_in[2];
    const float* Ws0 = (const float*)d_in[3];
    const float* Wn0 = (const float*)d_in[4];
    const float* b0  = (const float*)d_in[5];
    const float* Ws1 = (const float*)d_in[6];
    const float* Wn1 = (const float*)d_in[7];
    const float* b1  = (const float*)d_in[8];
    const float* Ws2 = (const float*)d_in[9];
    const float* Wn2 = (const float*)d_in[10];
    const float* b2  = (const float*)d_in[11];
    float* out = (float*)d_out;

    // --- CSR build ---
    k_zero_deg<<<(NN + 255) / 256, 256>>>();
    k_hist<<<(NE / 4 + 255) / 256, 256>>>(dst);
    k_scan_partial<<<NBLK_SCAN, 256>>>();
    k_scan_bsums<<<1, 128>>>();
    k_scan_final<<<NBLK_SCAN, 256>>>();
    k_scatter<<<(NE / 4 + 255) / 256, 256>>>(src, dst);

    // --- conversions ---
    k_convert_x<<<(NN * 128 / 4 + 255) / 256, 256>>>(x);
    k_convert_w<128><<<(256 * 128 + 255) / 256, 256>>>(Ws0, Wn0, 0);
    k_convert_w<128><<<(256 * 128 + 255) / 256, 256>>>(Ws1, Wn1, 1);
    k_convert_w<64><<<(128 * 128 + 255) / 256, 256>>>(Ws2, Wn2, 2);

    dim3 gagg((NN + 7) / 8, 1);
    dim3 gg2(4, NT);   // layers 0/1: N=256 -> 4 column strips of 64
    dim3 gg1(2, NT);   // layer 2:    N=128 -> 2

    // layer 0
    k_gemm_mma<<<gg2, 256>>>(0, 128, b0);
    k_agg_relu128<<<gagg, 256>>>();
    // layer 1
    k_gemm_mma<<<gg2, 256>>>(1, 128, b1);
    k_agg_relu128<<<gagg, 256>>>();
    // layer 2 (dim 64, agg after projection, fused log_softmax)
    k_gemm_mma<<<gg1, 256>>>(2, 64, b2);
    k_agg_lsm64<<<gagg, 256>>>(out);
}

// round 10
// speedup vs baseline: 2.0205x; 1.1488x over previous
#include <cuda_runtime.h>
#include <cuda_bf16.h>
#include <cuda_fp16.h>
#include <cstdint>
#include <cmath>

#define NN 100000
#define NE 1600000
#define NT 782                 // ceil(NN/128)
#define NPAD (NT * 128)        // 100096
#define NBLK_SCAN ((NN + 1023) / 1024)   // 98

// ---------------- static device scratch ----------------
__device__ int   g_deg[NN];
__device__ int   g_rowoff[NN + 1];
__device__ int   g_cursor[NN];
__device__ int   g_csr[NE];
__device__ int   g_bsum[128];
__device__ float g_invdeg[NN];
__device__ float g_selfp[(size_t)NN * 64];            // layer-2 self projection, fp32
__device__ __half g_selfph[(size_t)NN * 128];         // layer-0/1 self projection, fp16
__device__ __half g_tmph[(size_t)NN * 128];           // neighbor projection, fp16
__device__ __nv_bfloat16 g_ahi[(size_t)NPAD * 128];   // activations hi (x, then h)
__device__ __nv_bfloat16 g_alo[(size_t)NPAD * 128];   // activations lo
__device__ __nv_bfloat16 g_bhi[3 * 256 * 128];        // weights [n][k] hi, per layer
__device__ __nv_bfloat16 g_blo[3 * 256 * 128];        // weights lo

// ---------------- CSR preprocessing ----------------
__global__ void k_zero_deg() {
    int i = blockIdx.x * blockDim.x + threadIdx.x;
    if (i < NN) g_deg[i] = 0;
}
__global__ void k_hist(const int* __restrict__ dst) {
    int e4 = blockIdx.x * blockDim.x + threadIdx.x;
    if (e4 < NE / 4) {
        int4 d = ((const int4*)dst)[e4];
        atomicAdd(&g_deg[d.x], 1);
        atomicAdd(&g_deg[d.y], 1);
        atomicAdd(&g_deg[d.z], 1);
        atomicAdd(&g_deg[d.w], 1);
    }
}
__global__ void k_scan_partial() {
    __shared__ int wsum[8];
    int t = threadIdx.x;
    int base = blockIdx.x * 1024 + t * 4;
    int s = 0;
#pragma unroll
    for (int i = 0; i < 4; i++) { int idx = base + i; if (idx < NN) s += g_deg[idx]; }
#pragma unroll
    for (int o = 16; o; o >>= 1) s += __shfl_xor_sync(0xffffffffu, s, o);
    if ((t & 31) == 0) wsum[t >> 5] = s;
    __syncthreads();
    if (t == 0) {
        int tot = 0;
#pragma unroll
        for (int i = 0; i < 8; i++) tot += wsum[i];
        g_bsum[blockIdx.x] = tot;
    }
}
__global__ void k_scan_bsums() {
    __shared__ int ws[4];
    int t = threadIdx.x, lane = t & 31, wid = t >> 5;
    int v = (t < NBLK_SCAN) ? g_bsum[t] : 0;
    int inc = v;
#pragma unroll
    for (int o = 1; o < 32; o <<= 1) {
        int y = __shfl_up_sync(0xffffffffu, inc, o);
        if (lane >= o) inc += y;
    }
    if (lane == 31) ws[wid] = inc;
    __syncthreads();
    if (t == 0) {
        int acc = 0;
#pragma unroll
        for (int i = 0; i < 4; i++) { int x = ws[i]; ws[i] = acc; acc += x; }
    }
    __syncthreads();
    if (t < NBLK_SCAN) g_bsum[t] = ws[wid] + inc - v;
}
__global__ void k_scan_final() {
    __shared__ int wsum[8];
    int t = threadIdx.x;
    int base = blockIdx.x * 1024 + t * 4;
    int v[4];
    int s = 0;
#pragma unroll
    for (int i = 0; i < 4; i++) {
        int idx = base + i;
        v[i] = (idx < NN) ? g_deg[idx] : 0;
        s += v[i];
    }
    int lane = t & 31, wid = t >> 5;
    int inc = s;
#pragma unroll
    for (int o = 1; o < 32; o <<= 1) {
        int y = __shfl_up_sync(0xffffffffu, inc, o);
        if (lane >= o) inc += y;
    }
    if (lane == 31) wsum[wid] = inc;
    __syncthreads();
    if (t == 0) {
        int acc = 0;
#pragma unroll
        for (int i = 0; i < 8; i++) { int x = wsum[i]; wsum[i] = acc; acc += x; }
    }
    __syncthreads();
    int excl = g_bsum[blockIdx.x] + wsum[wid] + (inc - s);
#pragma unroll
    for (int i = 0; i < 4; i++) {
        int idx = base + i;
        if (idx < NN) {
            g_rowoff[idx] = excl;
            g_cursor[idx] = excl;
            g_invdeg[idx] = 1.0f / fmaxf((float)v[i], 1.0f);
            excl += v[i];
        }
    }
    if (blockIdx.x == 0 && t == 0) g_rowoff[NN] = NE;
}
__global__ void k_scatter(const int* __restrict__ src, const int* __restrict__ dst) {
    int e4 = blockIdx.x * blockDim.x + threadIdx.x;
    if (e4 < NE / 4) {
        int4 sv = ((const int4*)src)[e4];
        int4 dv = ((const int4*)dst)[e4];
        g_csr[atomicAdd(&g_cursor[dv.x], 1)] = sv.x;
        g_csr[atomicAdd(&g_cursor[dv.y], 1)] = sv.y;
        g_csr[atomicAdd(&g_cursor[dv.z], 1)] = sv.z;
        g_csr[atomicAdd(&g_cursor[dv.w], 1)] = sv.w;
    }
}

// ---------------- fp32 -> bf16 hi/lo ----------------
__device__ __forceinline__ uint32_t pack_bf(__nv_bfloat16 a, __nv_bfloat16 b) {
    return (uint32_t)__bfloat16_as_ushort(a) | ((uint32_t)__bfloat16_as_ushort(b) << 16);
}
__device__ __forceinline__ void split4(float4 v, uint2& hi, uint2& lo) {
    __nv_bfloat16 h0 = __float2bfloat16(v.x), h1 = __float2bfloat16(v.y);
    __nv_bfloat16 h2 = __float2bfloat16(v.z), h3 = __float2bfloat16(v.w);
    __nv_bfloat16 l0 = __float2bfloat16(v.x - __bfloat162float(h0));
    __nv_bfloat16 l1 = __float2bfloat16(v.y - __bfloat162float(h1));
    __nv_bfloat16 l2 = __float2bfloat16(v.z - __bfloat162float(h2));
    __nv_bfloat16 l3 = __float2bfloat16(v.w - __bfloat162float(h3));
    hi.x = pack_bf(h0, h1); hi.y = pack_bf(h2, h3);
    lo.x = pack_bf(l0, l1); lo.y = pack_bf(l2, l3);
}
__global__ void k_convert_x(const float* __restrict__ x) {
    size_t i = (size_t)(blockIdx.x * blockDim.x + threadIdx.x) * 4;
    if (i >= (size_t)NN * 128) return;
    float4 v = *(const float4*)(x + i);
    uint2 hi, lo;
    split4(v, hi, lo);
    *(uint2*)(g_ahi + i) = hi;
    *(uint2*)(g_alo + i) = lo;
}
template <int NO1>
__global__ void k_convert_w(const float* __restrict__ Ws, const float* __restrict__ Wn, int layer) {
    const int NO = 2 * NO1;
    int idx = blockIdx.x * blockDim.x + threadIdx.x;   // n*128 + k
    if (idx >= NO * 128) return;
    int n = idx >> 7, k = idx & 127;
    float v = (n < NO1) ? Ws[k * NO1 + n] : Wn[k * NO1 + (n - NO1)];
    __nv_bfloat16 h = __float2bfloat16(v);
    __nv_bfloat16 l = __float2bfloat16(v - __bfloat162float(h));
    g_bhi[layer * 32768 + idx] = h;
    g_blo[layer * 32768 + idx] = l;
}

// ---------------- mma.sync / cp.async helpers ----------------
__device__ __forceinline__ uint32_t smem_u32(const void* p) {
    uint32_t a;
    asm("{ .reg .u64 t; cvta.to.shared.u64 t, %1; cvt.u32.u64 %0, t; }" : "=r"(a) : "l"(p));
    return a;
}
__device__ __forceinline__ void ldm_x4(uint32_t& d0, uint32_t& d1, uint32_t& d2, uint32_t& d3,
                                       uint32_t addr) {
    asm volatile("ldmatrix.sync.aligned.m8n8.x4.shared.b16 {%0,%1,%2,%3}, [%4];"
        : "=r"(d0), "=r"(d1), "=r"(d2), "=r"(d3) : "r"(addr));
}
__device__ __forceinline__ void mma_bf16(float* c, const uint32_t* a, uint32_t b0, uint32_t b1) {
    asm volatile("mma.sync.aligned.m16n8k16.row.col.f32.bf16.bf16.f32 "
        "{%0,%1,%2,%3}, {%4,%5,%6,%7}, {%8,%9}, {%0,%1,%2,%3};"
        : "+f"(c[0]), "+f"(c[1]), "+f"(c[2]), "+f"(c[3])
        : "r"(a[0]), "r"(a[1]), "r"(a[2]), "r"(a[3]), "r"(b0), "r"(b1));
}
__device__ __forceinline__ void cp16(uint32_t dst, const void* src) {
    asm volatile("cp.async.cg.shared.global [%0], [%1], 16;" :: "r"(dst), "l"(src) : "memory");
}
#define CP_COMMIT() asm volatile("cp.async.commit_group;" ::: "memory")
#define CP_WAIT1()  asm volatile("cp.async.wait_group 1;" ::: "memory")
#define CP_WAIT0()  asm volatile("cp.async.wait_group 0;" ::: "memory")

// ---------------- cp.async double-buffered mma GEMM (48KB static) ----------
// CTA: D[128,64] = A_tile[128,128] @ B_strip[64,128]^T, 3-term bf16 split.
// K in 4 chunks of 32, 2-stage ping-pong (24KB/stage). SMEM rows = 32 bf16 =
// 64B = 4 x 16B chunks; chunk c of row r at r*64 + ((c ^ ((r>>1)&3))*16).
// NO1=128: selfp->g_selfph fp16; NO1=64: selfp->g_selfp fp32. tmp->g_tmph fp16.
template <int NO1>
__global__ __launch_bounds__(256) void k_gemm_mma(int layer, const float* __restrict__ bias) {
    constexpr int STG = 24576;
    constexpr int A_HI = 0, A_LO = 8192, B_HI = 16384, B_LO = 20480;
    __shared__ __align__(16) char smem[49152];
    uint32_t sb = smem_u32(smem);
    int tid = threadIdx.x, wid = tid >> 5, lane = tid & 31;
    int tile = blockIdx.y;
    int bn0 = blockIdx.x * 64;

    const __nv_bfloat16* ah = g_ahi + (size_t)tile * 16384;
    const __nv_bfloat16* al = g_alo + (size_t)tile * 16384;
    const __nv_bfloat16* bh = g_bhi + layer * 32768 + (size_t)bn0 * 128;
    const __nv_bfloat16* bl = g_blo + layer * 32768 + (size_t)bn0 * 128;

    int wm = (wid & 3) * 32;
    int wn = (wid >> 2) * 32;
    int lrow = lane & 15, lchunk = lane >> 4;

    // stage loader: kc = K chunk index (0..3)
    auto load_stage = [&](int kc, uint32_t sbase) {
#pragma unroll
        for (int ii = 0; ii < 2; ii++) {           // A: 512 chunks hi+lo
            int i = tid + ii * 256;
            int r = i >> 2, c = i & 3;
            uint32_t off = (uint32_t)r * 64u + (uint32_t)((c ^ ((r >> 1) & 3)) << 4);
            cp16(sb + sbase + A_HI + off, ah + r * 128 + kc * 32 + c * 8);
            cp16(sb + sbase + A_LO + off, al + r * 128 + kc * 32 + c * 8);
        }
        {                                           // B: 256 chunks hi+lo
            int r = tid >> 2, c = tid & 3;
            uint32_t off = (uint32_t)r * 64u + (uint32_t)((c ^ ((r >> 1) & 3)) << 4);
            cp16(sb + sbase + B_HI + off, bh + r * 128 + kc * 32 + c * 8);
            cp16(sb + sbase + B_LO + off, bl + r * 128 + kc * 32 + c * 8);
        }
    };

    float acc[2][4][4];
#pragma unroll
    for (int i = 0; i < 2; i++)
#pragma unroll
        for (int j = 0; j < 4; j++)
#pragma unroll
            for (int q = 0; q < 4; q++) acc[i][j][q] = 0.0f;

    load_stage(0, 0);
    CP_COMMIT();

#pragma unroll
    for (int kc = 0; kc < 4; kc++) {
        uint32_t cur = (uint32_t)(kc & 1) * STG;
        if (kc < 3) {
            load_stage(kc + 1, (uint32_t)((kc + 1) & 1) * STG);
            CP_COMMIT();
            CP_WAIT1();
        } else {
            CP_WAIT0();
        }
        __syncthreads();

#pragma unroll
        for (int ks = 0; ks < 2; ks++) {            // 2 k-steps of 16 per stage
            int c0 = 2 * ks;
            uint32_t ahi[2][4], alo[2][4];
#pragma unroll
            for (int mt = 0; mt < 2; mt++) {
                int r = wm + mt * 16 + lrow;
                uint32_t off = (uint32_t)r * 64u
                             + (uint32_t)(((c0 + lchunk) ^ ((r >> 1) & 3)) << 4);
                ldm_x4(ahi[mt][0], ahi[mt][1], ahi[mt][2], ahi[mt][3], sb + cur + A_HI + off);
                ldm_x4(alo[mt][0], alo[mt][1], alo[mt][2], alo[mt][3], sb + cur + A_LO + off);
            }
            uint32_t bhi[4][2], blo[4][2];
#pragma unroll
            for (int nq = 0; nq < 2; nq++) {
                int r = wn + nq * 16 + lrow;
                uint32_t off = (uint32_t)r * 64u
                             + (uint32_t)(((c0 + lchunk) ^ ((r >> 1) & 3)) << 4);
                uint32_t t0, t1, t2, t3;
                ldm_x4(t0, t1, t2, t3, sb + cur + B_HI + off);
                bhi[2 * nq][0] = t0; bhi[2 * nq][1] = t2;
                bhi[2 * nq + 1][0] = t1; bhi[2 * nq + 1][1] = t3;
                ldm_x4(t0, t1, t2, t3, sb + cur + B_LO + off);
                blo[2 * nq][0] = t0; blo[2 * nq][1] = t2;
                blo[2 * nq + 1][0] = t1; blo[2 * nq + 1][1] = t3;
            }
#pragma unroll
            for (int mt = 0; mt < 2; mt++)
#pragma unroll
                for (int nt = 0; nt < 4; nt++) {
                    mma_bf16(acc[mt][nt], ahi[mt], bhi[nt][0], bhi[nt][1]);
                    mma_bf16(acc[mt][nt], ahi[mt], blo[nt][0], blo[nt][1]);
                    mma_bf16(acc[mt][nt], alo[mt], bhi[nt][0], bhi[nt][1]);
                }
        }
        __syncthreads();
    }

    // epilogue
    int qrow = lane >> 2;
    int qcol = (lane & 3) * 2;
#pragma unroll
    for (int mt = 0; mt < 2; mt++) {
#pragma unroll
        for (int nt = 0; nt < 4; nt++) {
            int r0 = tile * 128 + wm + mt * 16 + qrow;
            int gc = bn0 + wn + nt * 8 + qcol;
            float2 v0 = make_float2(acc[mt][nt][0], acc[mt][nt][1]);
            float2 v1 = make_float2(acc[mt][nt][2], acc[mt][nt][3]);
            if (gc < NO1) {
                float2 bv = *(const float2*)(bias + gc);
                v0.x += bv.x; v0.y += bv.y;
                v1.x += bv.x; v1.y += bv.y;
                if (NO1 == 128) {   // fp16 selfp (layers 0/1)
                    if (r0 < NN)
                        *(__half2*)(g_selfph + (size_t)r0 * 128 + gc) = __floats2half2_rn(v0.x, v0.y);
                    if (r0 + 8 < NN)
                        *(__half2*)(g_selfph + (size_t)(r0 + 8) * 128 + gc) = __floats2half2_rn(v1.x, v1.y);
                } else {            // fp32 selfp (layer 2)
                    if (r0 < NN)     *(float2*)(g_selfp + (size_t)r0 * NO1 + gc) = v0;
                    if (r0 + 8 < NN) *(float2*)(g_selfp + (size_t)(r0 + 8) * NO1 + gc) = v1;
                }
            } else {
                int tc = gc - NO1;
                if (r0 < NN)
                    *(__half2*)(g_tmph + (size_t)r0 * NO1 + tc) = __floats2half2_rn(v0.x, v0.y);
                if (r0 + 8 < NN)
                    *(__half2*)(g_tmph + (size_t)(r0 + 8) * NO1 + tc) = __floats2half2_rn(v1.x, v1.y);
            }
        }
    }
}

// ---------------- aggregation (fp16 gather, fp32 accumulate) ----------------
__device__ __forceinline__ void add_h4(float4& a, uint2 v) {
    __half2 p0 = *reinterpret_cast<__half2*>(&v.x);
    __half2 p1 = *reinterpret_cast<__half2*>(&v.y);
    float2 f0 = __half22float2(p0), f1 = __half22float2(p1);
    a.x += f0.x; a.y += f0.y; a.z += f1.x; a.w += f1.y;
}

// h = relu(selfph + invdeg * sum tmp[nbr]), dim 128; writes bf16 hi/lo
__global__ __launch_bounds__(256) void k_agg_relu128() {
    int w = (blockIdx.x * blockDim.x + threadIdx.x) >> 5;
    int lane = threadIdx.x & 31;
    if (w >= NN) return;
    int beg = g_rowoff[w], end = g_rowoff[w + 1];
    float4 acc0 = make_float4(0.f, 0.f, 0.f, 0.f);
    float4 acc1 = make_float4(0.f, 0.f, 0.f, 0.f);
    int i = beg;
    for (; i + 3 < end; i += 4) {
        int u0 = g_csr[i], u1 = g_csr[i + 1], u2 = g_csr[i + 2], u3 = g_csr[i + 3];
        uint2 v0 = *(const uint2*)(g_tmph + (size_t)u0 * 128 + lane * 4);
        uint2 v1 = *(const uint2*)(g_tmph + (size_t)u1 * 128 + lane * 4);
        uint2 v2 = *(const uint2*)(g_tmph + (size_t)u2 * 128 + lane * 4);
        uint2 v3 = *(const uint2*)(g_tmph + (size_t)u3 * 128 + lane * 4);
        add_h4(acc0, v0); add_h4(acc1, v1); add_h4(acc0, v2); add_h4(acc1, v3);
    }
    for (; i < end; i++) {
        int u0 = g_csr[i];
        uint2 v0 = *(const uint2*)(g_tmph + (size_t)u0 * 128 + lane * 4);
        add_h4(acc0, v0);
    }
    float s = g_invdeg[w];
    float4 sp;
    {
        uint2 spv = *(const uint2*)(g_selfph + (size_t)w * 128 + lane * 4);
        __half2 p0 = *reinterpret_cast<__half2*>(&spv.x);
        __half2 p1 = *reinterpret_cast<__half2*>(&spv.y);
        float2 f0 = __half22float2(p0), f1 = __half22float2(p1);
        sp = make_float4(f0.x, f0.y, f1.x, f1.y);
    }
    float4 o;
    o.x = fmaxf(fmaf(acc0.x + acc1.x, s, sp.x), 0.f);
    o.y = fmaxf(fmaf(acc0.y + acc1.y, s, sp.y), 0.f);
    o.z = fmaxf(fmaf(acc0.z + acc1.z, s, sp.z), 0.f);
    o.w = fmaxf(fmaf(acc0.w + acc1.w, s, sp.w), 0.f);
    uint2 hi, lo;
    split4(o, hi, lo);
    *(uint2*)(g_ahi + (size_t)w * 128 + lane * 4) = hi;
    *(uint2*)(g_alo + (size_t)w * 128 + lane * 4) = lo;
}

// final layer: dim 64, fp32 selfp, fused log_softmax
__global__ __launch_bounds__(256) void k_agg_lsm64(float* __restrict__ out) {
    int w = (blockIdx.x * blockDim.x + threadIdx.x) >> 5;
    int lane = threadIdx.x & 31;
    if (w >= NN) return;
    int beg = g_rowoff[w], end = g_rowoff[w + 1];
    float2 acc0 = make_float2(0.f, 0.f);
    float2 acc1 = make_float2(0.f, 0.f);
    int i = beg;
    for (; i + 3 < end; i += 4) {
        int u0 = g_csr[i], u1 = g_csr[i + 1], u2 = g_csr[i + 2], u3 = g_csr[i + 3];
        float2 f0 = __half22float2(*(const __half2*)(g_tmph + (size_t)u0 * 64 + lane * 2));
        float2 f1 = __half22float2(*(const __half2*)(g_tmph + (size_t)u1 * 64 + lane * 2));
        float2 f2 = __half22float2(*(const __half2*)(g_tmph + (size_t)u2 * 64 + lane * 2));
        float2 f3 = __half22float2(*(const __half2*)(g_tmph + (size_t)u3 * 64 + lane * 2));
        acc0.x += f0.x + f2.x; acc0.y += f0.y + f2.y;
        acc1.x += f1.x + f3.x; acc1.y += f1.y + f3.y;
    }
    for (; i < end; i++) {
        int u0 = g_csr[i];
        float2 f0 = __half22float2(*(const __half2*)(g_tmph + (size_t)u0 * 64 + lane * 2));
        acc0.x += f0.x; acc0.y += f0.y;
    }
    float s = g_invdeg[w];
    float2 sp = *(const float2*)(g_selfp + (size_t)w * 64 + lane * 2);
    float v0 = fmaf(acc0.x + acc1.x, s, sp.x);
    float v1 = fmaf(acc0.y + acc1.y, s, sp.y);
    float m = fmaxf(v0, v1);
#pragma unroll
    for (int o = 16; o; o >>= 1) m = fmaxf(m, __shfl_xor_sync(0xffffffffu, m, o));
    float e = expf(v0 - m) + expf(v1 - m);
#pragma unroll
    for (int o = 16; o; o >>= 1) e += __shfl_xor_sync(0xffffffffu, e, o);
    float lse = m + logf(e);
    float2 res = make_float2(v0 - lse, v1 - lse);
    *(float2*)(out + (size_t)w * 64 + lane * 2) = res;
}

// ---------------- launch: PURE kernel launches, zero other host API ----------------
extern "C" void kernel_launch(void* const* d_in, const int* in_sizes, int n_in,
                              void* d_out, int out_size) {
    const float* x   = (const float*)d_in[0];
    const int*   src = (const int*)d_in[1];
    const int*   dst = (const int*)d_in[2];
    const float* Ws0 = (const float*)d_in[3];
    const float* Wn0 = (const float*)d_in[4];
    const float* b0  = (const float*)d_in[5];
    const float* Ws1 = (const float*)d_in[6];
    const float* Wn1 = (const float*)d_in[7];
    const float* b1  = (const float*)d_in[8];
    const float* Ws2 = (const float*)d_in[9];
    const float* Wn2 = (const float*)d_in[10];
    const float* b2  = (const float*)d_in[11];
    float* out = (float*)d_out;

    // --- CSR build ---
    k_zero_deg<<<(NN + 255) / 256, 256>>>();
    k_hist<<<(NE / 4 + 255) / 256, 256>>>(dst);
    k_scan_partial<<<NBLK_SCAN, 256>>>();
    k_scan_bsums<<<1, 128>>>();
    k_scan_final<<<NBLK_SCAN, 256>>>();
    k_scatter<<<(NE / 4 + 255) / 256, 256>>>(src, dst);

    // --- conversions ---
    k_convert_x<<<(NN * 128 / 4 + 255) / 256, 256>>>(x);
    k_convert_w<128><<<(256 * 128 + 255) / 256, 256>>>(Ws0, Wn0, 0);
    k_convert_w<128><<<(256 * 128 + 255) / 256, 256>>>(Ws1, Wn1, 1);
    k_convert_w<64><<<(128 * 128 + 255) / 256, 256>>>(Ws2, Wn2, 2);

    dim3 gagg((NN + 7) / 8, 1);
    dim3 gg2(4, NT);   // layers 0/1: N=256 -> 4 column strips of 64
    dim3 gg1(2, NT);   // layer 2:    N=128 -> 2

    // layer 0
    k_gemm_mma<128><<<gg2, 256>>>(0, b0);
    k_agg_relu128<<<gagg, 256>>>();
    // layer 1
    k_gemm_mma<128><<<gg2, 256>>>(1, b1);
    k_agg_relu128<<<gagg, 256>>>();
    // layer 2 (dim 64, agg after projection, fused log_softmax)
    k_gemm_mma<64><<<gg1, 256>>>(2, b2);
    k_agg_lsm64<<<gagg, 256>>>(out);
}

// round 11
// speedup vs baseline: 2.0722x; 1.0256x over previous
#include <cuda_runtime.h>
#include <cuda_bf16.h>
#include <cuda_fp16.h>
#include <cstdint>
#include <cmath>

#define NN 100000
#define NE 1600000
#define NT 782                 // ceil(NN/128)
#define NPAD (NT * 128)        // 100096
#define NBLK_SCAN ((NN + 1023) / 1024)   // 98

// ---------------- static device scratch ----------------
__device__ int   g_deg[NN];
__device__ int   g_rowoff[NN + 1];
__device__ int   g_cursor[NN];
__device__ int   g_csr[NE];
__device__ int   g_bsum[128];
__device__ float g_invdeg[NN];
__device__ float g_selfp[(size_t)NN * 64];            // layer-2 self projection, fp32
__device__ __half g_selfph[(size_t)NN * 128];         // layer-0/1 self projection, fp16
__device__ __half g_tmph[(size_t)NN * 128];           // neighbor projection, fp16
__device__ __nv_bfloat16 g_ahi[(size_t)NPAD * 128];   // activations hi (x, then h)
__device__ __nv_bfloat16 g_alo[(size_t)NPAD * 128];   // activations lo
__device__ __nv_bfloat16 g_bhi[3 * 256 * 128];        // weights [n][k] hi, per layer
__device__ __nv_bfloat16 g_blo[3 * 256 * 128];        // weights lo

// ---------------- fp32 -> bf16 hi/lo helpers ----------------
__device__ __forceinline__ uint32_t pack_bf(__nv_bfloat16 a, __nv_bfloat16 b) {
    return (uint32_t)__bfloat16_as_ushort(a) | ((uint32_t)__bfloat16_as_ushort(b) << 16);
}
__device__ __forceinline__ void split4(float4 v, uint2& hi, uint2& lo) {
    __nv_bfloat16 h0 = __float2bfloat16(v.x), h1 = __float2bfloat16(v.y);
    __nv_bfloat16 h2 = __float2bfloat16(v.z), h3 = __float2bfloat16(v.w);
    __nv_bfloat16 l0 = __float2bfloat16(v.x - __bfloat162float(h0));
    __nv_bfloat16 l1 = __float2bfloat16(v.y - __bfloat162float(h1));
    __nv_bfloat16 l2 = __float2bfloat16(v.z - __bfloat162float(h2));
    __nv_bfloat16 l3 = __float2bfloat16(v.w - __bfloat162float(h3));
    hi.x = pack_bf(h0, h1); hi.y = pack_bf(h2, h3);
    lo.x = pack_bf(l0, l1); lo.y = pack_bf(l2, l3);
}

// ---------------- fused setup: zero_deg + convert_x + convert_w(all layers) ----------
// grid covers NN*128/4 = 3.2M threads; extra jobs branch on thread id.
__global__ void k_setup(const float* __restrict__ x,
                        const float* __restrict__ Ws0, const float* __restrict__ Wn0,
                        const float* __restrict__ Ws1, const float* __restrict__ Wn1,
                        const float* __restrict__ Ws2, const float* __restrict__ Wn2) {
    int t = blockIdx.x * blockDim.x + threadIdx.x;
    // job 1: zero degree counters
    if (t < NN) g_deg[t] = 0;
    // job 2: weight conversion (81920 elements total)
    if (t < 81920) {
        int layer, NO1, base;
        const float *Ws, *Wn;
        if (t < 32768)      { layer = 0; NO1 = 128; Ws = Ws0; Wn = Wn0; base = t; }
        else if (t < 65536) { layer = 1; NO1 = 128; Ws = Ws1; Wn = Wn1; base = t - 32768; }
        else                { layer = 2; NO1 = 64;  Ws = Ws2; Wn = Wn2; base = t - 65536; }
        int n = base >> 7, k = base & 127;
        float v = (n < NO1) ? Ws[k * NO1 + n] : Wn[k * NO1 + (n - NO1)];
        __nv_bfloat16 h = __float2bfloat16(v);
        __nv_bfloat16 l = __float2bfloat16(v - __bfloat162float(h));
        g_bhi[layer * 32768 + base] = h;
        g_blo[layer * 32768 + base] = l;
    }
    // job 3: x -> bf16 hi/lo
    size_t i = (size_t)t * 4;
    if (i < (size_t)NN * 128) {
        float4 v = *(const float4*)(x + i);
        uint2 hi, lo;
        split4(v, hi, lo);
        *(uint2*)(g_ahi + i) = hi;
        *(uint2*)(g_alo + i) = lo;
    }
}

// ---------------- CSR preprocessing ----------------
__global__ void k_hist(const int* __restrict__ dst) {
    int e4 = blockIdx.x * blockDim.x + threadIdx.x;
    if (e4 < NE / 4) {
        int4 d = ((const int4*)dst)[e4];
        atomicAdd(&g_deg[d.x], 1);
        atomicAdd(&g_deg[d.y], 1);
        atomicAdd(&g_deg[d.z], 1);
        atomicAdd(&g_deg[d.w], 1);
    }
}
__global__ void k_scan_partial() {
    __shared__ int wsum[8];
    int t = threadIdx.x;
    int base = blockIdx.x * 1024 + t * 4;
    int s = 0;
#pragma unroll
    for (int i = 0; i < 4; i++) { int idx = base + i; if (idx < NN) s += g_deg[idx]; }
#pragma unroll
    for (int o = 16; o; o >>= 1) s += __shfl_xor_sync(0xffffffffu, s, o);
    if ((t & 31) == 0) wsum[t >> 5] = s;
    __syncthreads();
    if (t == 0) {
        int tot = 0;
#pragma unroll
        for (int i = 0; i < 8; i++) tot += wsum[i];
        g_bsum[blockIdx.x] = tot;
    }
}
__global__ void k_scan_bsums() {
    __shared__ int ws[4];
    int t = threadIdx.x, lane = t & 31, wid = t >> 5;
    int v = (t < NBLK_SCAN) ? g_bsum[t] : 0;
    int inc = v;
#pragma unroll
    for (int o = 1; o < 32; o <<= 1) {
        int y = __shfl_up_sync(0xffffffffu, inc, o);
        if (lane >= o) inc += y;
    }
    if (lane == 31) ws[wid] = inc;
    __syncthreads();
    if (t == 0) {
        int acc = 0;
#pragma unroll
        for (int i = 0; i < 4; i++) { int x = ws[i]; ws[i] = acc; acc += x; }
    }
    __syncthreads();
    if (t < NBLK_SCAN) g_bsum[t] = ws[wid] + inc - v;
}
__global__ void k_scan_final() {
    __shared__ int wsum[8];
    int t = threadIdx.x;
    int base = blockIdx.x * 1024 + t * 4;
    int v[4];
    int s = 0;
#pragma unroll
    for (int i = 0; i < 4; i++) {
        int idx = base + i;
        v[i] = (idx < NN) ? g_deg[idx] : 0;
        s += v[i];
    }
    int lane = t & 31, wid = t >> 5;
    int inc = s;
#pragma unroll
    for (int o = 1; o < 32; o <<= 1) {
        int y = __shfl_up_sync(0xffffffffu, inc, o);
        if (lane >= o) inc += y;
    }
    if (lane == 31) wsum[wid] = inc;
    __syncthreads();
    if (t == 0) {
        int acc = 0;
#pragma unroll
        for (int i = 0; i < 8; i++) { int x = wsum[i]; wsum[i] = acc; acc += x; }
    }
    __syncthreads();
    int excl = g_bsum[blockIdx.x] + wsum[wid] + (inc - s);
#pragma unroll
    for (int i = 0; i < 4; i++) {
        int idx = base + i;
        if (idx < NN) {
            g_rowoff[idx] = excl;
            g_cursor[idx] = excl;
            g_invdeg[idx] = 1.0f / fmaxf((float)v[i], 1.0f);
            excl += v[i];
        }
    }
    if (blockIdx.x == 0 && t == 0) g_rowoff[NN] = NE;
}
__global__ void k_scatter(const int* __restrict__ src, const int* __restrict__ dst) {
    int e4 = blockIdx.x * blockDim.x + threadIdx.x;
    if (e4 < NE / 4) {
        int4 sv = ((const int4*)src)[e4];
        int4 dv = ((const int4*)dst)[e4];
        g_csr[atomicAdd(&g_cursor[dv.x], 1)] = sv.x;
        g_csr[atomicAdd(&g_cursor[dv.y], 1)] = sv.y;
        g_csr[atomicAdd(&g_cursor[dv.z], 1)] = sv.z;
        g_csr[atomicAdd(&g_cursor[dv.w], 1)] = sv.w;
    }
}

// ---------------- mma.sync / cp.async helpers ----------------
__device__ __forceinline__ uint32_t smem_u32(const void* p) {
    uint32_t a;
    asm("{ .reg .u64 t; cvta.to.shared.u64 t, %1; cvt.u32.u64 %0, t; }" : "=r"(a) : "l"(p));
    return a;
}
__device__ __forceinline__ void ldm_x4(uint32_t& d0, uint32_t& d1, uint32_t& d2, uint32_t& d3,
                                       uint32_t addr) {
    asm volatile("ldmatrix.sync.aligned.m8n8.x4.shared.b16 {%0,%1,%2,%3}, [%4];"
        : "=r"(d0), "=r"(d1), "=r"(d2), "=r"(d3) : "r"(addr));
}
__device__ __forceinline__ void mma_bf16(float* c, const uint32_t* a, uint32_t b0, uint32_t b1) {
    asm volatile("mma.sync.aligned.m16n8k16.row.col.f32.bf16.bf16.f32 "
        "{%0,%1,%2,%3}, {%4,%5,%6,%7}, {%8,%9}, {%0,%1,%2,%3};"
        : "+f"(c[0]), "+f"(c[1]), "+f"(c[2]), "+f"(c[3])
        : "r"(a[0]), "r"(a[1]), "r"(a[2]), "r"(a[3]), "r"(b0), "r"(b1));
}
__device__ __forceinline__ void cp16(uint32_t dst, const void* src) {
    asm volatile("cp.async.cg.shared.global [%0], [%1], 16;" :: "r"(dst), "l"(src) : "memory");
}
#define CP_COMMIT() asm volatile("cp.async.commit_group;" ::: "memory")
#define CP_WAIT1()  asm volatile("cp.async.wait_group 1;" ::: "memory")
#define CP_WAIT0()  asm volatile("cp.async.wait_group 0;" ::: "memory")

// ---------------- cp.async double-buffered mma GEMM (48KB static) ----------
template <int NO1>
__global__ __launch_bounds__(256) void k_gemm_mma(int layer, const float* __restrict__ bias) {
    constexpr int STG = 24576;
    constexpr int A_HI = 0, A_LO = 8192, B_HI = 16384, B_LO = 20480;
    __shared__ __align__(16) char smem[49152];
    uint32_t sb = smem_u32(smem);
    int tid = threadIdx.x, wid = tid >> 5, lane = tid & 31;
    int tile = blockIdx.y;
    int bn0 = blockIdx.x * 64;

    const __nv_bfloat16* ah = g_ahi + (size_t)tile * 16384;
    const __nv_bfloat16* al = g_alo + (size_t)tile * 16384;
    const __nv_bfloat16* bh = g_bhi + layer * 32768 + (size_t)bn0 * 128;
    const __nv_bfloat16* bl = g_blo + layer * 32768 + (size_t)bn0 * 128;

    int wm = (wid & 3) * 32;
    int wn = (wid >> 2) * 32;
    int lrow = lane & 15, lchunk = lane >> 4;

    auto load_stage = [&](int kc, uint32_t sbase) {
#pragma unroll
        for (int ii = 0; ii < 2; ii++) {
            int i = tid + ii * 256;
            int r = i >> 2, c = i & 3;
            uint32_t off = (uint32_t)r * 64u + (uint32_t)((c ^ ((r >> 1) & 3)) << 4);
            cp16(sb + sbase + A_HI + off, ah + r * 128 + kc * 32 + c * 8);
            cp16(sb + sbase + A_LO + off, al + r * 128 + kc * 32 + c * 8);
        }
        {
            int r = tid >> 2, c = tid & 3;
            uint32_t off = (uint32_t)r * 64u + (uint32_t)((c ^ ((r >> 1) & 3)) << 4);
            cp16(sb + sbase + B_HI + off, bh + r * 128 + kc * 32 + c * 8);
            cp16(sb + sbase + B_LO + off, bl + r * 128 + kc * 32 + c * 8);
        }
    };

    float acc[2][4][4];
#pragma unroll
    for (int i = 0; i < 2; i++)
#pragma unroll
        for (int j = 0; j < 4; j++)
#pragma unroll
            for (int q = 0; q < 4; q++) acc[i][j][q] = 0.0f;

    load_stage(0, 0);
    CP_COMMIT();

#pragma unroll
    for (int kc = 0; kc < 4; kc++) {
        uint32_t cur = (uint32_t)(kc & 1) * STG;
        if (kc < 3) {
            load_stage(kc + 1, (uint32_t)((kc + 1) & 1) * STG);
            CP_COMMIT();
            CP_WAIT1();
        } else {
            CP_WAIT0();
        }
        __syncthreads();

#pragma unroll
        for (int ks = 0; ks < 2; ks++) {
            int c0 = 2 * ks;
            uint32_t ahi[2][4], alo[2][4];
#pragma unroll
            for (int mt = 0; mt < 2; mt++) {
                int r = wm + mt * 16 + lrow;
                uint32_t off = (uint32_t)r * 64u
                             + (uint32_t)(((c0 + lchunk) ^ ((r >> 1) & 3)) << 4);
                ldm_x4(ahi[mt][0], ahi[mt][1], ahi[mt][2], ahi[mt][3], sb + cur + A_HI + off);
                ldm_x4(alo[mt][0], alo[mt][1], alo[mt][2], alo[mt][3], sb + cur + A_LO + off);
            }
            uint32_t bhi[4][2], blo[4][2];
#pragma unroll
            for (int nq = 0; nq < 2; nq++) {
                int r = wn + nq * 16 + lrow;
                uint32_t off = (uint32_t)r * 64u
                             + (uint32_t)(((c0 + lchunk) ^ ((r >> 1) & 3)) << 4);
                uint32_t t0, t1, t2, t3;
                ldm_x4(t0, t1, t2, t3, sb + cur + B_HI + off);
                bhi[2 * nq][0] = t0; bhi[2 * nq][1] = t2;
                bhi[2 * nq + 1][0] = t1; bhi[2 * nq + 1][1] = t3;
                ldm_x4(t0, t1, t2, t3, sb + cur + B_LO + off);
                blo[2 * nq][0] = t0; blo[2 * nq][1] = t2;
                blo[2 * nq + 1][0] = t1; blo[2 * nq + 1][1] = t3;
            }
#pragma unroll
            for (int mt = 0; mt < 2; mt++)
#pragma unroll
                for (int nt = 0; nt < 4; nt++) {
                    mma_bf16(acc[mt][nt], ahi[mt], bhi[nt][0], bhi[nt][1]);
                    mma_bf16(acc[mt][nt], ahi[mt], blo[nt][0], blo[nt][1]);
                    mma_bf16(acc[mt][nt], alo[mt], bhi[nt][0], bhi[nt][1]);
                }
        }
        __syncthreads();
    }

    // epilogue
    int qrow = lane >> 2;
    int qcol = (lane & 3) * 2;
#pragma unroll
    for (int mt = 0; mt < 2; mt++) {
#pragma unroll
        for (int nt = 0; nt < 4; nt++) {
            int r0 = tile * 128 + wm + mt * 16 + qrow;
            int gc = bn0 + wn + nt * 8 + qcol;
            float2 v0 = make_float2(acc[mt][nt][0], acc[mt][nt][1]);
            float2 v1 = make_float2(acc[mt][nt][2], acc[mt][nt][3]);
            if (gc < NO1) {
                float2 bv = *(const float2*)(bias + gc);
                v0.x += bv.x; v0.y += bv.y;
                v1.x += bv.x; v1.y += bv.y;
                if (NO1 == 128) {
                    if (r0 < NN)
                        *(__half2*)(g_selfph + (size_t)r0 * 128 + gc) = __floats2half2_rn(v0.x, v0.y);
                    if (r0 + 8 < NN)
                        *(__half2*)(g_selfph + (size_t)(r0 + 8) * 128 + gc) = __floats2half2_rn(v1.x, v1.y);
                } else {
                    if (r0 < NN)     *(float2*)(g_selfp + (size_t)r0 * NO1 + gc) = v0;
                    if (r0 + 8 < NN) *(float2*)(g_selfp + (size_t)(r0 + 8) * NO1 + gc) = v1;
                }
            } else {
                int tc = gc - NO1;
                if (r0 < NN)
                    *(__half2*)(g_tmph + (size_t)r0 * NO1 + tc) = __floats2half2_rn(v0.x, v0.y);
                if (r0 + 8 < NN)
                    *(__half2*)(g_tmph + (size_t)(r0 + 8) * NO1 + tc) = __floats2half2_rn(v1.x, v1.y);
            }
        }
    }
}

// ---------------- aggregation (fp16 gather, fp32 accumulate, 8-wide MLP) ----------------
__device__ __forceinline__ void add_h4(float4& a, uint2 v) {
    __half2 p0 = *reinterpret_cast<__half2*>(&v.x);
    __half2 p1 = *reinterpret_cast<__half2*>(&v.y);
    float2 f0 = __half22float2(p0), f1 = __half22float2(p1);
    a.x += f0.x; a.y += f0.y; a.z += f1.x; a.w += f1.y;
}

__global__ __launch_bounds__(256) void k_agg_relu128() {
    int w = (blockIdx.x * blockDim.x + threadIdx.x) >> 5;
    int lane = threadIdx.x & 31;
    if (w >= NN) return;
    int beg = g_rowoff[w], end = g_rowoff[w + 1];
    float4 acc0 = make_float4(0.f, 0.f, 0.f, 0.f);
    float4 acc1 = make_float4(0.f, 0.f, 0.f, 0.f);
    int i = beg;
    for (; i + 7 < end; i += 8) {
        int u[8];
#pragma unroll
        for (int j = 0; j < 8; j++) u[j] = g_csr[i + j];
        uint2 v[8];
#pragma unroll
        for (int j = 0; j < 8; j++)
            v[j] = *(const uint2*)(g_tmph + (size_t)u[j] * 128 + lane * 4);
#pragma unroll
        for (int j = 0; j < 8; j++) add_h4((j & 1) ? acc1 : acc0, v[j]);
    }
    for (; i + 1 < end; i += 2) {
        int u0 = g_csr[i], u1 = g_csr[i + 1];
        uint2 v0 = *(const uint2*)(g_tmph + (size_t)u0 * 128 + lane * 4);
        uint2 v1 = *(const uint2*)(g_tmph + (size_t)u1 * 128 + lane * 4);
        add_h4(acc0, v0); add_h4(acc1, v1);
    }
    if (i < end) {
        int u0 = g_csr[i];
        uint2 v0 = *(const uint2*)(g_tmph + (size_t)u0 * 128 + lane * 4);
        add_h4(acc0, v0);
    }
    float s = g_invdeg[w];
    float4 sp;
    {
        uint2 spv = *(const uint2*)(g_selfph + (size_t)w * 128 + lane * 4);
        __half2 p0 = *reinterpret_cast<__half2*>(&spv.x);
        __half2 p1 = *reinterpret_cast<__half2*>(&spv.y);
        float2 f0 = __half22float2(p0), f1 = __half22float2(p1);
        sp = make_float4(f0.x, f0.y, f1.x, f1.y);
    }
    float4 o;
    o.x = fmaxf(fmaf(acc0.x + acc1.x, s, sp.x), 0.f);
    o.y = fmaxf(fmaf(acc0.y + acc1.y, s, sp.y), 0.f);
    o.z = fmaxf(fmaf(acc0.z + acc1.z, s, sp.z), 0.f);
    o.w = fmaxf(fmaf(acc0.w + acc1.w, s, sp.w), 0.f);
    uint2 hi, lo;
    split4(o, hi, lo);
    *(uint2*)(g_ahi + (size_t)w * 128 + lane * 4) = hi;
    *(uint2*)(g_alo + (size_t)w * 128 + lane * 4) = lo;
}

__global__ __launch_bounds__(256) void k_agg_lsm64(float* __restrict__ out) {
    int w = (blockIdx.x * blockDim.x + threadIdx.x) >> 5;
    int lane = threadIdx.x & 31;
    if (w >= NN) return;
    int beg = g_rowoff[w], end = g_rowoff[w + 1];
    float2 acc0 = make_float2(0.f, 0.f);
    float2 acc1 = make_float2(0.f, 0.f);
    int i = beg;
    for (; i + 7 < end; i += 8) {
        int u[8];
#pragma unroll
        for (int j = 0; j < 8; j++) u[j] = g_csr[i + j];
        __half2 v[8];
#pragma unroll
        for (int j = 0; j < 8; j++)
            v[j] = *(const __half2*)(g_tmph + (size_t)u[j] * 64 + lane * 2);
#pragma unroll
        for (int j = 0; j < 8; j++) {
            float2 f = __half22float2(v[j]);
            if (j & 1) { acc1.x += f.x; acc1.y += f.y; }
            else       { acc0.x += f.x; acc0.y += f.y; }
        }
    }
    for (; i < end; i++) {
        int u0 = g_csr[i];
        float2 f0 = __half22float2(*(const __half2*)(g_tmph + (size_t)u0 * 64 + lane * 2));
        acc0.x += f0.x; acc0.y += f0.y;
    }
    float s = g_invdeg[w];
    float2 sp = *(const float2*)(g_selfp + (size_t)w * 64 + lane * 2);
    float v0 = fmaf(acc0.x + acc1.x, s, sp.x);
    float v1 = fmaf(acc0.y + acc1.y, s, sp.y);
    float m = fmaxf(v0, v1);
#pragma unroll
    for (int o = 16; o; o >>= 1) m = fmaxf(m, __shfl_xor_sync(0xffffffffu, m, o));
    float e = expf(v0 - m) + expf(v1 - m);
#pragma unroll
    for (int o = 16; o; o >>= 1) e += __shfl_xor_sync(0xffffffffu, e, o);
    float lse = m + logf(e);
    float2 res = make_float2(v0 - lse, v1 - lse);
    *(float2*)(out + (size_t)w * 64 + lane * 2) = res;
}

// ---------------- launch: PURE kernel launches, zero other host API ----------------
extern "C" void kernel_launch(void* const* d_in, const int* in_sizes, int n_in,
                              void* d_out, int out_size) {
    const float* x   = (const float*)d_in[0];
    const int*   src = (const int*)d_in[1];
    const int*   dst = (const int*)d_in[2];
    const float* Ws0 = (const float*)d_in[3];
    const float* Wn0 = (const float*)d_in[4];
    const float* b0  = (const float*)d_in[5];
    const float* Ws1 = (const float*)d_in[6];
    const float* Wn1 = (const float*)d_in[7];
    const float* b1  = (const float*)d_in[8];
    const float* Ws2 = (const float*)d_in[9];
    const float* Wn2 = (const float*)d_in[10];
    const float* b2  = (const float*)d_in[11];
    float* out = (float*)d_out;

    // --- fused setup (zero_deg + convert_x + convert_w all layers) ---
    k_setup<<<(NN * 128 / 4 + 255) / 256, 256>>>(x, Ws0, Wn0, Ws1, Wn1, Ws2, Wn2);

    // --- CSR build ---
    k_hist<<<(NE / 4 + 255) / 256, 256>>>(dst);
    k_scan_partial<<<NBLK_SCAN, 256>>>();
    k_scan_bsums<<<1, 128>>>();
    k_scan_final<<<NBLK_SCAN, 256>>>();
    k_scatter<<<(NE / 4 + 255) / 256, 256>>>(src, dst);

    dim3 gagg((NN + 7) / 8, 1);
    dim3 gg2(4, NT);   // layers 0/1: N=256 -> 4 column strips of 64
    dim3 gg1(2, NT);   // layer 2:    N=128 -> 2

    // layer 0
    k_gemm_mma<128><<<gg2, 256>>>(0, b0);
    k_agg_relu128<<<gagg, 256>>>();
    // layer 1
    k_gemm_mma<128><<<gg2, 256>>>(1, b1);
    k_agg_relu128<<<gagg, 256>>>();
    // layer 2 (dim 64, agg after projection, fused log_softmax)
    k_gemm_mma<64><<<gg1, 256>>>(2, b2);
    k_agg_lsm64<<<gagg, 256>>>(out);
}

// round 12
// speedup vs baseline: 2.4461x; 1.1804x over previous
#include <cuda_runtime.h>
#include <cuda_fp16.h>
#include <cstdint>
#include <cmath>

#define NN 100000
#define NE 1600000
#define NT 782                 // ceil(NN/128)
#define NPAD (NT * 128)        // 100096
#define NBLK_SCAN ((NN + 1023) / 1024)   // 98

// ---------------- static device scratch ----------------
__device__ int   g_deg[NN];
__device__ int   g_rowoff[NN + 1];
__device__ int   g_cursor[NN];
__device__ int   g_csr[NE];
__device__ int   g_bsum[128];
__device__ float g_invdeg[NN];
__device__ float g_selfp[(size_t)NN * 64];            // layer-2 self projection, fp32
__device__ __half g_selfph[(size_t)NN * 128];         // layer-0/1 self projection, fp16
__device__ __half g_tmph[(size_t)NN * 128];           // neighbor projection, fp16
__device__ __half g_a[(size_t)NPAD * 128];            // activations fp16 (x, then h)
__device__ __half g_bh[3 * 256 * 128];                // weights [n][k] hi, fp16, per layer
__device__ __half g_bl[3 * 256 * 128];                // weights lo (residual), fp16

// ---------------- fused setup: zero_deg + convert_x + convert_w ----------
__global__ void k_setup(const float* __restrict__ x,
                        const float* __restrict__ Ws0, const float* __restrict__ Wn0,
                        const float* __restrict__ Ws1, const float* __restrict__ Wn1,
                        const float* __restrict__ Ws2, const float* __restrict__ Wn2) {
    int t = blockIdx.x * blockDim.x + threadIdx.x;
    if (t < NN) g_deg[t] = 0;
    if (t < 81920) {
        int layer, NO1, base;
        const float *Ws, *Wn;
        if (t < 32768)      { layer = 0; NO1 = 128; Ws = Ws0; Wn = Wn0; base = t; }
        else if (t < 65536) { layer = 1; NO1 = 128; Ws = Ws1; Wn = Wn1; base = t - 32768; }
        else                { layer = 2; NO1 = 64;  Ws = Ws2; Wn = Wn2; base = t - 65536; }
        int n = base >> 7, k = base & 127;
        float v = (n < NO1) ? Ws[k * NO1 + n] : Wn[k * NO1 + (n - NO1)];
        __half h = __float2half_rn(v);
        __half l = __float2half_rn(v - __half2float(h));
        g_bh[layer * 32768 + base] = h;
        g_bl[layer * 32768 + base] = l;
    }
    size_t i = (size_t)t * 4;
    if (i < (size_t)NN * 128) {
        float4 v = *(const float4*)(x + i);
        uint2 p;
        __half2 h0 = __floats2half2_rn(v.x, v.y);
        __half2 h1 = __floats2half2_rn(v.z, v.w);
        p.x = *reinterpret_cast<uint32_t*>(&h0);
        p.y = *reinterpret_cast<uint32_t*>(&h1);
        *(uint2*)(g_a + i) = p;
    }
}

// ---------------- CSR preprocessing ----------------
__global__ void k_hist(const int* __restrict__ dst) {
    int e4 = blockIdx.x * blockDim.x + threadIdx.x;
    if (e4 < NE / 4) {
        int4 d = ((const int4*)dst)[e4];
        atomicAdd(&g_deg[d.x], 1);
        atomicAdd(&g_deg[d.y], 1);
        atomicAdd(&g_deg[d.z], 1);
        atomicAdd(&g_deg[d.w], 1);
    }
}
__global__ void k_scan_partial() {
    __shared__ int wsum[8];
    int t = threadIdx.x;
    int base = blockIdx.x * 1024 + t * 4;
    int s = 0;
#pragma unroll
    for (int i = 0; i < 4; i++) { int idx = base + i; if (idx < NN) s += g_deg[idx]; }
#pragma unroll
    for (int o = 16; o; o >>= 1) s += __shfl_xor_sync(0xffffffffu, s, o);
    if ((t & 31) == 0) wsum[t >> 5] = s;
    __syncthreads();
    if (t == 0) {
        int tot = 0;
#pragma unroll
        for (int i = 0; i < 8; i++) tot += wsum[i];
        g_bsum[blockIdx.x] = tot;
    }
}
__global__ void k_scan_bsums() {
    __shared__ int ws[4];
    int t = threadIdx.x, lane = t & 31, wid = t >> 5;
    int v = (t < NBLK_SCAN) ? g_bsum[t] : 0;
    int inc = v;
#pragma unroll
    for (int o = 1; o < 32; o <<= 1) {
        int y = __shfl_up_sync(0xffffffffu, inc, o);
        if (lane >= o) inc += y;
    }
    if (lane == 31) ws[wid] = inc;
    __syncthreads();
    if (t == 0) {
        int acc = 0;
#pragma unroll
        for (int i = 0; i < 4; i++) { int x = ws[i]; ws[i] = acc; acc += x; }
    }
    __syncthreads();
    if (t < NBLK_SCAN) g_bsum[t] = ws[wid] + inc - v;
}
__global__ void k_scan_final() {
    __shared__ int wsum[8];
    int t = threadIdx.x;
    int base = blockIdx.x * 1024 + t * 4;
    int v[4];
    int s = 0;
#pragma unroll
    for (int i = 0; i < 4; i++) {
        int idx = base + i;
        v[i] = (idx < NN) ? g_deg[idx] : 0;
        s += v[i];
    }
    int lane = t & 31, wid = t >> 5;
    int inc = s;
#pragma unroll
    for (int o = 1; o < 32; o <<= 1) {
        int y = __shfl_up_sync(0xffffffffu, inc, o);
        if (lane >= o) inc += y;
    }
    if (lane == 31) wsum[wid] = inc;
    __syncthreads();
    if (t == 0) {
        int acc = 0;
#pragma unroll
        for (int i = 0; i < 8; i++) { int x = wsum[i]; wsum[i] = acc; acc += x; }
    }
    __syncthreads();
    int excl = g_bsum[blockIdx.x] + wsum[wid] + (inc - s);
#pragma unroll
    for (int i = 0; i < 4; i++) {
        int idx = base + i;
        if (idx < NN) {
            g_rowoff[idx] = excl;
            g_cursor[idx] = excl;
            g_invdeg[idx] = 1.0f / fmaxf((float)v[i], 1.0f);
            excl += v[i];
        }
    }
    if (blockIdx.x == 0 && t == 0) g_rowoff[NN] = NE;
}
__global__ void k_scatter(const int* __restrict__ src, const int* __restrict__ dst) {
    int e4 = blockIdx.x * blockDim.x + threadIdx.x;
    if (e4 < NE / 4) {
        int4 sv = ((const int4*)src)[e4];
        int4 dv = ((const int4*)dst)[e4];
        g_csr[atomicAdd(&g_cursor[dv.x], 1)] = sv.x;
        g_csr[atomicAdd(&g_cursor[dv.y], 1)] = sv.y;
        g_csr[atomicAdd(&g_cursor[dv.z], 1)] = sv.z;
        g_csr[atomicAdd(&g_cursor[dv.w], 1)] = sv.w;
    }
}

// ---------------- mma.sync / cp.async helpers ----------------
__device__ __forceinline__ uint32_t smem_u32(const void* p) {
    uint32_t a;
    asm("{ .reg .u64 t; cvta.to.shared.u64 t, %1; cvt.u32.u64 %0, t; }" : "=r"(a) : "l"(p));
    return a;
}
__device__ __forceinline__ void ldm_x4(uint32_t& d0, uint32_t& d1, uint32_t& d2, uint32_t& d3,
                                       uint32_t addr) {
    asm volatile("ldmatrix.sync.aligned.m8n8.x4.shared.b16 {%0,%1,%2,%3}, [%4];"
        : "=r"(d0), "=r"(d1), "=r"(d2), "=r"(d3) : "r"(addr));
}
__device__ __forceinline__ void mma_f16(float* c, const uint32_t* a, uint32_t b0, uint32_t b1) {
    asm volatile("mma.sync.aligned.m16n8k16.row.col.f32.f16.f16.f32 "
        "{%0,%1,%2,%3}, {%4,%5,%6,%7}, {%8,%9}, {%0,%1,%2,%3};"
        : "+f"(c[0]), "+f"(c[1]), "+f"(c[2]), "+f"(c[3])
        : "r"(a[0]), "r"(a[1]), "r"(a[2]), "r"(a[3]), "r"(b0), "r"(b1));
}
__device__ __forceinline__ void cp16(uint32_t dst, const void* src) {
    asm volatile("cp.async.cg.shared.global [%0], [%1], 16;" :: "r"(dst), "l"(src) : "memory");
}
#define CP_COMMIT() asm volatile("cp.async.commit_group;" ::: "memory")
#define CP_WAIT1()  asm volatile("cp.async.wait_group 1;" ::: "memory")
#define CP_WAIT0()  asm volatile("cp.async.wait_group 0;" ::: "memory")

// ---------------- cp.async double-buffered mma GEMM, BN=128 (48KB static) ----------
// CTA: D[128,128] = A_tile[128,128] @ B_strip[128,128]^T, 2-term split
// (A16*Bhi + A16*Blo). K in 4 chunks of 32, 2-stage ping-pong (24KB/stage).
// SMEM rows = 32 fp16 = 64B = 4 x 16B chunks; chunk c of row r at
// r*64 + ((c ^ ((r>>1)&3))*16).
// Global col gc = blockIdx.x*128 + local; gc < NO1 -> selfp, else tmp.
template <int NO1>
__global__ __launch_bounds__(256) void k_gemm_mma(int layer, const float* __restrict__ bias) {
    constexpr int STG = 24576;
    constexpr int A_S = 0, B_HI = 8192, B_LO = 16384;
    __shared__ __align__(16) char smem[49152];
    uint32_t sb = smem_u32(smem);
    int tid = threadIdx.x, wid = tid >> 5, lane = tid & 31;
    int tile = blockIdx.y;
    int bn0 = blockIdx.x * 128;

    const __half* ap = g_a + (size_t)tile * 16384;
    const __half* bh = g_bh + layer * 32768 + (size_t)bn0 * 128;
    const __half* bl = g_bl + layer * 32768 + (size_t)bn0 * 128;

    int wm = (wid & 3) * 32;    // 4 warps over 128 rows
    int wn = (wid >> 2) * 64;   // 2 warps over 128 cols
    int lrow = lane & 15, lchunk = lane >> 4;

    auto load_stage = [&](int kc, uint32_t sbase) {
#pragma unroll
        for (int ii = 0; ii < 2; ii++) {           // A: 512 chunks
            int i = tid + ii * 256;
            int r = i >> 2, c = i & 3;
            uint32_t off = (uint32_t)r * 64u + (uint32_t)((c ^ ((r >> 1) & 3)) << 4);
            cp16(sb + sbase + A_S + off, ap + r * 128 + kc * 32 + c * 8);
        }
#pragma unroll
        for (int ii = 0; ii < 2; ii++) {           // B: 512 chunks, hi+lo
            int i = tid + ii * 256;
            int r = i >> 2, c = i & 3;
            uint32_t off = (uint32_t)r * 64u + (uint32_t)((c ^ ((r >> 1) & 3)) << 4);
            cp16(sb + sbase + B_HI + off, bh + r * 128 + kc * 32 + c * 8);
            cp16(sb + sbase + B_LO + off, bl + r * 128 + kc * 32 + c * 8);
        }
    };

    float acc[2][8][4];
#pragma unroll
    for (int i = 0; i < 2; i++)
#pragma unroll
        for (int j = 0; j < 8; j++)
#pragma unroll
            for (int q = 0; q < 4; q++) acc[i][j][q] = 0.0f;

    load_stage(0, 0);
    CP_COMMIT();

#pragma unroll
    for (int kc = 0; kc < 4; kc++) {
        uint32_t cur = (uint32_t)(kc & 1) * STG;
        if (kc < 3) {
            load_stage(kc + 1, (uint32_t)((kc + 1) & 1) * STG);
            CP_COMMIT();
            CP_WAIT1();
        } else {
            CP_WAIT0();
        }
        __syncthreads();

#pragma unroll
        for (int ks = 0; ks < 2; ks++) {
            int c0 = 2 * ks;
            uint32_t av[2][4];
#pragma unroll
            for (int mt = 0; mt < 2; mt++) {
                int r = wm + mt * 16 + lrow;
                uint32_t off = (uint32_t)r * 64u
                             + (uint32_t)(((c0 + lchunk) ^ ((r >> 1) & 3)) << 4);
                ldm_x4(av[mt][0], av[mt][1], av[mt][2], av[mt][3], sb + cur + A_S + off);
            }
            uint32_t bhi[8][2], blo[8][2];
#pragma unroll
            for (int nq = 0; nq < 4; nq++) {
                int r = wn + nq * 16 + lrow;
                uint32_t off = (uint32_t)r * 64u
                             + (uint32_t)(((c0 + lchunk) ^ ((r >> 1) & 3)) << 4);
                uint32_t t0, t1, t2, t3;
                ldm_x4(t0, t1, t2, t3, sb + cur + B_HI + off);
                bhi[2 * nq][0] = t0; bhi[2 * nq][1] = t2;
                bhi[2 * nq + 1][0] = t1; bhi[2 * nq + 1][1] = t3;
                ldm_x4(t0, t1, t2, t3, sb + cur + B_LO + off);
                blo[2 * nq][0] = t0; blo[2 * nq][1] = t2;
                blo[2 * nq + 1][0] = t1; blo[2 * nq + 1][1] = t3;
            }
#pragma unroll
            for (int mt = 0; mt < 2; mt++)
#pragma unroll
                for (int nt = 0; nt < 8; nt++) {
                    mma_f16(acc[mt][nt], av[mt], bhi[nt][0], bhi[nt][1]);
                    mma_f16(acc[mt][nt], av[mt], blo[nt][0], blo[nt][1]);
                }
        }
        __syncthreads();
    }

    // epilogue
    int qrow = lane >> 2;
    int qcol = (lane & 3) * 2;
#pragma unroll
    for (int mt = 0; mt < 2; mt++) {
#pragma unroll
        for (int nt = 0; nt < 8; nt++) {
            int r0 = tile * 128 + wm + mt * 16 + qrow;
            int gc = bn0 + wn + nt * 8 + qcol;
            float2 v0 = make_float2(acc[mt][nt][0], acc[mt][nt][1]);
            float2 v1 = make_float2(acc[mt][nt][2], acc[mt][nt][3]);
            if (gc < NO1) {
                float2 bv = *(const float2*)(bias + gc);
                v0.x += bv.x; v0.y += bv.y;
                v1.x += bv.x; v1.y += bv.y;
                if (NO1 == 128) {
                    if (r0 < NN)
                        *(__half2*)(g_selfph + (size_t)r0 * 128 + gc) = __floats2half2_rn(v0.x, v0.y);
                    if (r0 + 8 < NN)
                        *(__half2*)(g_selfph + (size_t)(r0 + 8) * 128 + gc) = __floats2half2_rn(v1.x, v1.y);
                } else {
                    if (r0 < NN)     *(float2*)(g_selfp + (size_t)r0 * NO1 + gc) = v0;
                    if (r0 + 8 < NN) *(float2*)(g_selfp + (size_t)(r0 + 8) * NO1 + gc) = v1;
                }
            } else {
                int tc = gc - NO1;
                if (r0 < NN)
                    *(__half2*)(g_tmph + (size_t)r0 * NO1 + tc) = __floats2half2_rn(v0.x, v0.y);
                if (r0 + 8 < NN)
                    *(__half2*)(g_tmph + (size_t)(r0 + 8) * NO1 + tc) = __floats2half2_rn(v1.x, v1.y);
            }
        }
    }
}

// ---------------- aggregation (fp16 gather, fp32 accumulate, 8-wide MLP) ----------------
__device__ __forceinline__ void add_h4(float4& a, uint2 v) {
    __half2 p0 = *reinterpret_cast<__half2*>(&v.x);
    __half2 p1 = *reinterpret_cast<__half2*>(&v.y);
    float2 f0 = __half22float2(p0), f1 = __half22float2(p1);
    a.x += f0.x; a.y += f0.y; a.z += f1.x; a.w += f1.y;
}

// h = relu(selfph + invdeg * sum tmp[nbr]), dim 128; writes fp16 activations
__global__ __launch_bounds__(256) void k_agg_relu128() {
    int w = (blockIdx.x * blockDim.x + threadIdx.x) >> 5;
    int lane = threadIdx.x & 31;
    if (w >= NN) return;
    int beg = g_rowoff[w], end = g_rowoff[w + 1];
    float4 acc0 = make_float4(0.f, 0.f, 0.f, 0.f);
    float4 acc1 = make_float4(0.f, 0.f, 0.f, 0.f);
    int i = beg;
    for (; i + 7 < end; i += 8) {
        int u[8];
#pragma unroll
        for (int j = 0; j < 8; j++) u[j] = g_csr[i + j];
        uint2 v[8];
#pragma unroll
        for (int j = 0; j < 8; j++)
            v[j] = *(const uint2*)(g_tmph + (size_t)u[j] * 128 + lane * 4);
#pragma unroll
        for (int j = 0; j < 8; j++) add_h4((j & 1) ? acc1 : acc0, v[j]);
    }
    for (; i + 1 < end; i += 2) {
        int u0 = g_csr[i], u1 = g_csr[i + 1];
        uint2 v0 = *(const uint2*)(g_tmph + (size_t)u0 * 128 + lane * 4);
        uint2 v1 = *(const uint2*)(g_tmph + (size_t)u1 * 128 + lane * 4);
        add_h4(acc0, v0); add_h4(acc1, v1);
    }
    if (i < end) {
        int u0 = g_csr[i];
        uint2 v0 = *(const uint2*)(g_tmph + (size_t)u0 * 128 + lane * 4);
        add_h4(acc0, v0);
    }
    float s = g_invdeg[w];
    float4 sp;
    {
        uint2 spv = *(const uint2*)(g_selfph + (size_t)w * 128 + lane * 4);
        __half2 p0 = *reinterpret_cast<__half2*>(&spv.x);
        __half2 p1 = *reinterpret_cast<__half2*>(&spv.y);
        float2 f0 = __half22float2(p0), f1 = __half22float2(p1);
        sp = make_float4(f0.x, f0.y, f1.x, f1.y);
    }
    float4 o;
    o.x = fmaxf(fmaf(acc0.x + acc1.x, s, sp.x), 0.f);
    o.y = fmaxf(fmaf(acc0.y + acc1.y, s, sp.y), 0.f);
    o.z = fmaxf(fmaf(acc0.z + acc1.z, s, sp.z), 0.f);
    o.w = fmaxf(fmaf(acc0.w + acc1.w, s, sp.w), 0.f);
    uint2 p;
    __half2 h0 = __floats2half2_rn(o.x, o.y);
    __half2 h1 = __floats2half2_rn(o.z, o.w);
    p.x = *reinterpret_cast<uint32_t*>(&h0);
    p.y = *reinterpret_cast<uint32_t*>(&h1);
    *(uint2*)(g_a + (size_t)w * 128 + lane * 4) = p;
}

// final layer: dim 64, fp32 selfp, fused log_softmax
__global__ __launch_bounds__(256) void k_agg_lsm64(float* __restrict__ out) {
    int w = (blockIdx.x * blockDim.x + threadIdx.x) >> 5;
    int lane = threadIdx.x & 31;
    if (w >= NN) return;
    int beg = g_rowoff[w], end = g_rowoff[w + 1];
    float2 acc0 = make_float2(0.f, 0.f);
    float2 acc1 = make_float2(0.f, 0.f);
    int i = beg;
    for (; i + 7 < end; i += 8) {
        int u[8];
#pragma unroll
        for (int j = 0; j < 8; j++) u[j] = g_csr[i + j];
        __half2 v[8];
#pragma unroll
        for (int j = 0; j < 8; j++)
            v[j] = *(const __half2*)(g_tmph + (size_t)u[j] * 64 + lane * 2);
#pragma unroll
        for (int j = 0; j < 8; j++) {
            float2 f = __half22float2(v[j]);
            if (j & 1) { acc1.x += f.x; acc1.y += f.y; }
            else       { acc0.x += f.x; acc0.y += f.y; }
        }
    }
    for (; i < end; i++) {
        int u0 = g_csr[i];
        float2 f0 = __half22float2(*(const __half2*)(g_tmph + (size_t)u0 * 64 + lane * 2));
        acc0.x += f0.x; acc0.y += f0.y;
    }
    float s = g_invdeg[w];
    float2 sp = *(const float2*)(g_selfp + (size_t)w * 64 + lane * 2);
    float v0 = fmaf(acc0.x + acc1.x, s, sp.x);
    float v1 = fmaf(acc0.y + acc1.y, s, sp.y);
    float m = fmaxf(v0, v1);
#pragma unroll
    for (int o = 16; o; o >>= 1) m = fmaxf(m, __shfl_xor_sync(0xffffffffu, m, o));
    float e = expf(v0 - m) + expf(v1 - m);
#pragma unroll
    for (int o = 16; o; o >>= 1) e += __shfl_xor_sync(0xffffffffu, e, o);
    float lse = m + logf(e);
    float2 res = make_float2(v0 - lse, v1 - lse);
    *(float2*)(out + (size_t)w * 64 + lane * 2) = res;
}

// ---------------- launch: PURE kernel launches, zero other host API ----------------
extern "C" void kernel_launch(void* const* d_in, const int* in_sizes, int n_in,
                              void* d_out, int out_size) {
    const float* x   = (const float*)d_in[0];
    const int*   src = (const int*)d_in[1];
    const int*   dst = (const int*)d_in[2];
    const float* Ws0 = (const float*)d_in[3];
    const float* Wn0 = (const float*)d_in[4];
    const float* b0  = (const float*)d_in[5];
    const float* Ws1 = (const float*)d_in[6];
    const float* Wn1 = (const float*)d_in[7];
    const float* b1  = (const float*)d_in[8];
    const float* Ws2 = (const float*)d_in[9];
    const float* Wn2 = (const float*)d_in[10];
    const float* b2  = (const float*)d_in[11];
    float* out = (float*)d_out;

    // --- fused setup ---
    k_setup<<<(NN * 128 / 4 + 255) / 256, 256>>>(x, Ws0, Wn0, Ws1, Wn1, Ws2, Wn2);

    // --- CSR build ---
    k_hist<<<(NE / 4 + 255) / 256, 256>>>(dst);
    k_scan_partial<<<NBLK_SCAN, 256>>>();
    k_scan_bsums<<<1, 128>>>();
    k_scan_final<<<NBLK_SCAN, 256>>>();
    k_scatter<<<(NE / 4 + 255) / 256, 256>>>(src, dst);

    dim3 gagg((NN + 7) / 8, 1);
    dim3 gg2(2, NT);   // layers 0/1: N=256 -> 2 column strips of 128
    dim3 gg1(1, NT);   // layer 2:    N=128 -> 1

    // layer 0
    k_gemm_mma<128><<<gg2, 256>>>(0, b0);
    k_agg_relu128<<<gagg, 256>>>();
    // layer 1
    k_gemm_mma<128><<<gg2, 256>>>(1, b1);
    k_agg_relu128<<<gagg, 256>>>();
    // layer 2 (dim 64, agg after projection, fused log_softmax)
    k_gemm_mma<64><<<gg1, 256>>>(2, b2);
    k_agg_lsm64<<<gagg, 256>>>(out);
}

// round 14
// speedup vs baseline: 2.7076x; 1.1069x over previous
#include <cuda_runtime.h>
#include <cuda_fp16.h>
#include <cstdint>
#include <cmath>

#define NN 100000
#define NE 1600000
#define NT 782                 // ceil(NN/128)
#define NPAD (NT * 128)        // 100096
#define NBLK_SCAN ((NN + 1023) / 1024)   // 98

// ---------------- static device scratch ----------------
__device__ int   g_deg[NN];
__device__ int   g_rowoff[NN + 1];
__device__ int   g_cursor[NN];
__device__ int   g_csr[NE];
__device__ int   g_bsum[128];
__device__ float g_invdeg[NN];
__device__ float g_selfp[(size_t)NN * 64];            // layer-2 self projection, fp32
__device__ __half g_selfph[(size_t)NN * 128];         // layer-0/1 self projection, fp16
__device__ __half g_tmph[(size_t)NN * 128];           // neighbor projection, fp16
__device__ __half g_a[(size_t)NPAD * 128];            // activations fp16 (x, then h)
__device__ __half g_bw[3 * 256 * 128];                // weights [n][k] fp16, per layer

// ---------------- fused setup: zero_deg + convert_x + convert_w ----------
__global__ void k_setup(const float* __restrict__ x,
                        const float* __restrict__ Ws0, const float* __restrict__ Wn0,
                        const float* __restrict__ Ws1, const float* __restrict__ Wn1,
                        const float* __restrict__ Ws2, const float* __restrict__ Wn2) {
    int t = blockIdx.x * blockDim.x + threadIdx.x;
    if (t < NN) g_deg[t] = 0;
    if (t < 81920) {
        int layer, NO1, base;
        const float *Ws, *Wn;
        if (t < 32768)      { layer = 0; NO1 = 128; Ws = Ws0; Wn = Wn0; base = t; }
        else if (t < 65536) { layer = 1; NO1 = 128; Ws = Ws1; Wn = Wn1; base = t - 32768; }
        else                { layer = 2; NO1 = 64;  Ws = Ws2; Wn = Wn2; base = t - 65536; }
        int n = base >> 7, k = base & 127;
        float v = (n < NO1) ? Ws[k * NO1 + n] : Wn[k * NO1 + (n - NO1)];
        g_bw[layer * 32768 + base] = __float2half_rn(v);
    }
    size_t i = (size_t)t * 4;
    if (i < (size_t)NN * 128) {
        float4 v = *(const float4*)(x + i);
        uint2 p;
        __half2 h0 = __floats2half2_rn(v.x, v.y);
        __half2 h1 = __floats2half2_rn(v.z, v.w);
        p.x = *reinterpret_cast<uint32_t*>(&h0);
        p.y = *reinterpret_cast<uint32_t*>(&h1);
        *(uint2*)(g_a + i) = p;
    }
}

// ---------------- CSR preprocessing ----------------
__global__ void k_hist(const int* __restrict__ dst) {
    int e4 = blockIdx.x * blockDim.x + threadIdx.x;
    if (e4 < NE / 4) {
        int4 d = ((const int4*)dst)[e4];
        atomicAdd(&g_deg[d.x], 1);
        atomicAdd(&g_deg[d.y], 1);
        atomicAdd(&g_deg[d.z], 1);
        atomicAdd(&g_deg[d.w], 1);
    }
}
__global__ void k_scan_partial() {
    __shared__ int wsum[8];
    int t = threadIdx.x;
    int base = blockIdx.x * 1024 + t * 4;
    int s = 0;
#pragma unroll
    for (int i = 0; i < 4; i++) { int idx = base + i; if (idx < NN) s += g_deg[idx]; }
#pragma unroll
    for (int o = 16; o; o >>= 1) s += __shfl_xor_sync(0xffffffffu, s, o);
    if ((t & 31) == 0) wsum[t >> 5] = s;
    __syncthreads();
    if (t == 0) {
        int tot = 0;
#pragma unroll
        for (int i = 0; i < 8; i++) tot += wsum[i];
        g_bsum[blockIdx.x] = tot;
    }
}
__global__ void k_scan_bsums() {
    __shared__ int ws[4];
    int t = threadIdx.x, lane = t & 31, wid = t >> 5;
    int v = (t < NBLK_SCAN) ? g_bsum[t] : 0;
    int inc = v;
#pragma unroll
    for (int o = 1; o < 32; o <<= 1) {
        int y = __shfl_up_sync(0xffffffffu, inc, o);
        if (lane >= o) inc += y;
    }
    if (lane == 31) ws[wid] = inc;
    __syncthreads();
    if (t == 0) {
        int acc = 0;
#pragma unroll
        for (int i = 0; i < 4; i++) { int x = ws[i]; ws[i] = acc; acc += x; }
    }
    __syncthreads();
    if (t < NBLK_SCAN) g_bsum[t] = ws[wid] + inc - v;
}
__global__ void k_scan_final() {
    __shared__ int wsum[8];
    int t = threadIdx.x;
    int base = blockIdx.x * 1024 + t * 4;
    int v[4];
    int s = 0;
#pragma unroll
    for (int i = 0; i < 4; i++) {
        int idx = base + i;
        v[i] = (idx < NN) ? g_deg[idx] : 0;
        s += v[i];
    }
    int lane = t & 31, wid = t >> 5;
    int inc = s;
#pragma unroll
    for (int o = 1; o < 32; o <<= 1) {
        int y = __shfl_up_sync(0xffffffffu, inc, o);
        if (lane >= o) inc += y;
    }
    if (lane == 31) wsum[wid] = inc;
    __syncthreads();
    if (t == 0) {
        int acc = 0;
#pragma unroll
        for (int i = 0; i < 8; i++) { int x = wsum[i]; wsum[i] = acc; acc += x; }
    }
    __syncthreads();
    int excl = g_bsum[blockIdx.x] + wsum[wid] + (inc - s);
#pragma unroll
    for (int i = 0; i < 4; i++) {
        int idx = base + i;
        if (idx < NN) {
            g_rowoff[idx] = excl;
            g_cursor[idx] = excl;
            g_invdeg[idx] = 1.0f / fmaxf((float)v[i], 1.0f);
            excl += v[i];
        }
    }
    if (blockIdx.x == 0 && t == 0) g_rowoff[NN] = NE;
}
__global__ void k_scatter(const int* __restrict__ src, const int* __restrict__ dst) {
    int e4 = blockIdx.x * blockDim.x + threadIdx.x;
    if (e4 < NE / 4) {
        int4 sv = ((const int4*)src)[e4];
        int4 dv = ((const int4*)dst)[e4];
        g_csr[atomicAdd(&g_cursor[dv.x], 1)] = sv.x;
        g_csr[atomicAdd(&g_cursor[dv.y], 1)] = sv.y;
        g_csr[atomicAdd(&g_cursor[dv.z], 1)] = sv.z;
        g_csr[atomicAdd(&g_cursor[dv.w], 1)] = sv.w;
    }
}

// ---------------- mma.sync / cp.async helpers ----------------
__device__ __forceinline__ uint32_t smem_u32(const void* p) {
    uint32_t a;
    asm("{ .reg .u64 t; cvta.to.shared.u64 t, %1; cvt.u32.u64 %0, t; }" : "=r"(a) : "l"(p));
    return a;
}
__device__ __forceinline__ void ldm_x4(uint32_t& d0, uint32_t& d1, uint32_t& d2, uint32_t& d3,
                                       uint32_t addr) {
    asm volatile("ldmatrix.sync.aligned.m8n8.x4.shared.b16 {%0,%1,%2,%3}, [%4];"
        : "=r"(d0), "=r"(d1), "=r"(d2), "=r"(d3) : "r"(addr));
}
__device__ __forceinline__ void mma_f16(float* c, const uint32_t* a, uint32_t b0, uint32_t b1) {
    asm volatile("mma.sync.aligned.m16n8k16.row.col.f32.f16.f16.f32 "
        "{%0,%1,%2,%3}, {%4,%5,%6,%7}, {%8,%9}, {%0,%1,%2,%3};"
        : "+f"(c[0]), "+f"(c[1]), "+f"(c[2]), "+f"(c[3])
        : "r"(a[0]), "r"(a[1]), "r"(a[2]), "r"(a[3]), "r"(b0), "r"(b1));
}
__device__ __forceinline__ void cp16(uint32_t dst, const void* src) {
    asm volatile("cp.async.cg.shared.global [%0], [%1], 16;" :: "r"(dst), "l"(src) : "memory");
}
#define CP_COMMIT() asm volatile("cp.async.commit_group;" ::: "memory")
#define CP_WAIT1()  asm volatile("cp.async.wait_group 1;" ::: "memory")
#define CP_WAIT0()  asm volatile("cp.async.wait_group 0;" ::: "memory")

// ---------------- cp.async double-buffered mma GEMM, BN=128, fp16 weights ----------
// CTA: D[128,128] = A_tile[128,128] @ B_strip[128,128]^T, single fp16 term.
// K in 4 chunks of 32, 2-stage ping-pong (16KB/stage, 32KB static total).
// SMEM rows = 32 fp16 = 64B = 4 x 16B chunks; chunk c of row r at
// r*64 + ((c ^ ((r>>1)&3))*16).
template <int NO1>
__global__ __launch_bounds__(256) void k_gemm_mma(int layer, const float* __restrict__ bias) {
    constexpr int STG = 16384;
    constexpr int A_S = 0, B_S = 8192;
    __shared__ __align__(16) char smem[32768];
    uint32_t sb = smem_u32(smem);
    int tid = threadIdx.x, wid = tid >> 5, lane = tid & 31;
    int tile = blockIdx.y;
    int bn0 = blockIdx.x * 128;

    const __half* ap = g_a + (size_t)tile * 16384;
    const __half* bw = g_bw + layer * 32768 + (size_t)bn0 * 128;

    int wm = (wid & 3) * 32;    // 4 warps over 128 rows
    int wn = (wid >> 2) * 64;   // 2 warps over 128 cols
    int lrow = lane & 15, lchunk = lane >> 4;

    auto load_stage = [&](int kc, uint32_t sbase) {
#pragma unroll
        for (int ii = 0; ii < 2; ii++) {           // A: 512 chunks
            int i = tid + ii * 256;
            int r = i >> 2, c = i & 3;
            uint32_t off = (uint32_t)r * 64u + (uint32_t)((c ^ ((r >> 1) & 3)) << 4);
            cp16(sb + sbase + A_S + off, ap + r * 128 + kc * 32 + c * 8);
        }
#pragma unroll
        for (int ii = 0; ii < 2; ii++) {           // B: 512 chunks
            int i = tid + ii * 256;
            int r = i >> 2, c = i & 3;
            uint32_t off = (uint32_t)r * 64u + (uint32_t)((c ^ ((r >> 1) & 3)) << 4);
            cp16(sb + sbase + B_S + off, bw + r * 128 + kc * 32 + c * 8);
        }
    };

    float acc[2][8][4];
#pragma unroll
    for (int i = 0; i < 2; i++)
#pragma unroll
        for (int j = 0; j < 8; j++)
#pragma unroll
            for (int q = 0; q < 4; q++) acc[i][j][q] = 0.0f;

    load_stage(0, 0);
    CP_COMMIT();

#pragma unroll
    for (int kc = 0; kc < 4; kc++) {
        uint32_t cur = (uint32_t)(kc & 1) * STG;
        if (kc < 3) {
            load_stage(kc + 1, (uint32_t)((kc + 1) & 1) * STG);
            CP_COMMIT();
            CP_WAIT1();
        } else {
            CP_WAIT0();
        }
        __syncthreads();

#pragma unroll
        for (int ks = 0; ks < 2; ks++) {
            int c0 = 2 * ks;
            uint32_t av[2][4];
#pragma unroll
            for (int mt = 0; mt < 2; mt++) {
                int r = wm + mt * 16 + lrow;
                uint32_t off = (uint32_t)r * 64u
                             + (uint32_t)(((c0 + lchunk) ^ ((r >> 1) & 3)) << 4);
                ldm_x4(av[mt][0], av[mt][1], av[mt][2], av[mt][3], sb + cur + A_S + off);
            }
            uint32_t bv[8][2];
#pragma unroll
            for (int nq = 0; nq < 4; nq++) {
                int r = wn + nq * 16 + lrow;
                uint32_t off = (uint32_t)r * 64u
                             + (uint32_t)(((c0 + lchunk) ^ ((r >> 1) & 3)) << 4);
                uint32_t t0, t1, t2, t3;
                ldm_x4(t0, t1, t2, t3, sb + cur + B_S + off);
                bv[2 * nq][0] = t0; bv[2 * nq][1] = t2;
                bv[2 * nq + 1][0] = t1; bv[2 * nq + 1][1] = t3;
            }
#pragma unroll
            for (int mt = 0; mt < 2; mt++)
#pragma unroll
                for (int nt = 0; nt < 8; nt++)
                    mma_f16(acc[mt][nt], av[mt], bv[nt][0], bv[nt][1]);
        }
        __syncthreads();
    }

    // epilogue
    int qrow = lane >> 2;
    int qcol = (lane & 3) * 2;
#pragma unroll
    for (int mt = 0; mt < 2; mt++) {
#pragma unroll
        for (int nt = 0; nt < 8; nt++) {
            int r0 = tile * 128 + wm + mt * 16 + qrow;
            int gc = bn0 + wn + nt * 8 + qcol;
            float2 v0 = make_float2(acc[mt][nt][0], acc[mt][nt][1]);
            float2 v1 = make_float2(acc[mt][nt][2], acc[mt][nt][3]);
            if (gc < NO1) {
                float2 bv = *(const float2*)(bias + gc);
                v0.x += bv.x; v0.y += bv.y;
                v1.x += bv.x; v1.y += bv.y;
                if (NO1 == 128) {
                    if (r0 < NN)
                        *(__half2*)(g_selfph + (size_t)r0 * 128 + gc) = __floats2half2_rn(v0.x, v0.y);
                    if (r0 + 8 < NN)
                        *(__half2*)(g_selfph + (size_t)(r0 + 8) * 128 + gc) = __floats2half2_rn(v1.x, v1.y);
                } else {
                    if (r0 < NN)     *(float2*)(g_selfp + (size_t)r0 * NO1 + gc) = v0;
                    if (r0 + 8 < NN) *(float2*)(g_selfp + (size_t)(r0 + 8) * NO1 + gc) = v1;
                }
            } else {
                int tc = gc - NO1;
                if (r0 < NN)
                    *(__half2*)(g_tmph + (size_t)r0 * NO1 + tc) = __floats2half2_rn(v0.x, v0.y);
                if (r0 + 8 < NN)
                    *(__half2*)(g_tmph + (size_t)(r0 + 8) * NO1 + tc) = __floats2half2_rn(v1.x, v1.y);
            }
        }
    }
}

// ---------------- aggregation (fp16 gather, fp32 accumulate, 8-wide MLP) ----------------
__device__ __forceinline__ void add_h4(float4& a, uint2 v) {
    __half2 p0 = *reinterpret_cast<__half2*>(&v.x);
    __half2 p1 = *reinterpret_cast<__half2*>(&v.y);
    float2 f0 = __half22float2(p0), f1 = __half22float2(p1);
    a.x += f0.x; a.y += f0.y; a.z += f1.x; a.w += f1.y;
}

__global__ __launch_bounds__(256) void k_agg_relu128() {
    int w = (blockIdx.x * blockDim.x + threadIdx.x) >> 5;
    int lane = threadIdx.x & 31;
    if (w >= NN) return;
    int beg = g_rowoff[w], end = g_rowoff[w + 1];
    float4 acc0 = make_float4(0.f, 0.f, 0.f, 0.f);
    float4 acc1 = make_float4(0.f, 0.f, 0.f, 0.f);
    int i = beg;
    for (; i + 7 < end; i += 8) {
        int u[8];
#pragma unroll
        for (int j = 0; j < 8; j++) u[j] = g_csr[i + j];
        uint2 v[8];
#pragma unroll
        for (int j = 0; j < 8; j++)
            v[j] = *(const uint2*)(g_tmph + (size_t)u[j] * 128 + lane * 4);
#pragma unroll
        for (int j = 0; j < 8; j++) add_h4((j & 1) ? acc1 : acc0, v[j]);
    }
    for (; i + 1 < end; i += 2) {
        int u0 = g_csr[i], u1 = g_csr[i + 1];
        uint2 v0 = *(const uint2*)(g_tmph + (size_t)u0 * 128 + lane * 4);
        uint2 v1 = *(const uint2*)(g_tmph + (size_t)u1 * 128 + lane * 4);
        add_h4(acc0, v0); add_h4(acc1, v1);
    }
    if (i < end) {
        int u0 = g_csr[i];
        uint2 v0 = *(const uint2*)(g_tmph + (size_t)u0 * 128 + lane * 4);
        add_h4(acc0, v0);
    }
    float s = g_invdeg[w];
    float4 sp;
    {
        uint2 spv = *(const uint2*)(g_selfph + (size_t)w * 128 + lane * 4);
        __half2 p0 = *reinterpret_cast<__half2*>(&spv.x);
        __half2 p1 = *reinterpret_cast<__half2*>(&spv.y);
        float2 f0 = __half22float2(p0), f1 = __half22float2(p1);
        sp = make_float4(f0.x, f0.y, f1.x, f1.y);
    }
    float4 o;
    o.x = fmaxf(fmaf(acc0.x + acc1.x, s, sp.x), 0.f);
    o.y = fmaxf(fmaf(acc0.y + acc1.y, s, sp.y), 0.f);
    o.z = fmaxf(fmaf(acc0.z + acc1.z, s, sp.z), 0.f);
    o.w = fmaxf(fmaf(acc0.w + acc1.w, s, sp.w), 0.f);
    uint2 p;
    __half2 h0 = __floats2half2_rn(o.x, o.y);
    __half2 h1 = __floats2half2_rn(o.z, o.w);
    p.x = *reinterpret_cast<uint32_t*>(&h0);
    p.y = *reinterpret_cast<uint32_t*>(&h1);
    *(uint2*)(g_a + (size_t)w * 128 + lane * 4) = p;
}

__global__ __launch_bounds__(256) void k_agg_lsm64(float* __restrict__ out) {
    int w = (blockIdx.x * blockDim.x + threadIdx.x) >> 5;
    int lane = threadIdx.x & 31;
    if (w >= NN) return;
    int beg = g_rowoff[w], end = g_rowoff[w + 1];
    float2 acc0 = make_float2(0.f, 0.f);
    float2 acc1 = make_float2(0.f, 0.f);
    int i = beg;
    for (; i + 7 < end; i += 8) {
        int u[8];
#pragma unroll
        for (int j = 0; j < 8; j++) u[j] = g_csr[i + j];
        __half2 v[8];
#pragma unroll
        for (int j = 0; j < 8; j++)
            v[j] = *(const __half2*)(g_tmph + (size_t)u[j] * 64 + lane * 2);
#pragma unroll
        for (int j = 0; j < 8; j++) {
            float2 f = __half22float2(v[j]);
            if (j & 1) { acc1.x += f.x; acc1.y += f.y; }
            else       { acc0.x += f.x; acc0.y += f.y; }
        }
    }
    for (; i < end; i++) {
        int u0 = g_csr[i];
        float2 f0 = __half22float2(*(const __half2*)(g_tmph + (size_t)u0 * 64 + lane * 2));
        acc0.x += f0.x; acc0.y += f0.y;
    }
    float s = g_invdeg[w];
    float2 sp = *(const float2*)(g_selfp + (size_t)w * 64 + lane * 2);
    float v0 = fmaf(acc0.x + acc1.x, s, sp.x);
    float v1 = fmaf(acc0.y + acc1.y, s, sp.y);
    float m = fmaxf(v0, v1);
#pragma unroll
    for (int o = 16; o; o >>= 1) m = fmaxf(m, __shfl_xor_sync(0xffffffffu, m, o));
    float e = expf(v0 - m) + expf(v1 - m);
#pragma unroll
    for (int o = 16; o; o >>= 1) e += __shfl_xor_sync(0xffffffffu, e, o);
    float lse = m + logf(e);
    float2 res = make_float2(v0 - lse, v1 - lse);
    *(float2*)(out + (size_t)w * 64 + lane * 2) = res;
}

// ---------------- launch: PURE kernel launches, zero other host API ----------------
extern "C" void kernel_launch(void* const* d_in, const int* in_sizes, int n_in,
                              void* d_out, int out_size) {
    const float* x   = (const float*)d_in[0];
    const int*   src = (const int*)d_in[1];
    const int*   dst = (const int*)d_in[2];
    const float* Ws0 = (const float*)d_in[3];
    const float* Wn0 = (const float*)d_in[4];
    const float* b0  = (const float*)d_in[5];
    const float* Ws1 = (const float*)d_in[6];
    const float* Wn1 = (const float*)d_in[7];
    const float* b1  = (const float*)d_in[8];
    const float* Ws2 = (const float*)d_in[9];
    const float* Wn2 = (const float*)d_in[10];
    const float* b2  = (const float*)d_in[11];
    float* out = (float*)d_out;

    // --- fused setup ---
    k_setup<<<(NN * 128 / 4 + 255) / 256, 256>>>(x, Ws0, Wn0, Ws1, Wn1, Ws2, Wn2);

    // --- CSR build ---
    k_hist<<<(NE / 4 + 255) / 256, 256>>>(dst);
    k_scan_partial<<<NBLK_SCAN, 256>>>();
    k_scan_bsums<<<1, 128>>>();
    k_scan_final<<<NBLK_SCAN, 256>>>();
    k_scatter<<<(NE / 4 + 255) / 256, 256>>>(src, dst);

    dim3 gagg((NN + 7) / 8, 1);
    dim3 gg2(2, NT);   // layers 0/1: N=256 -> 2 column strips of 128
    dim3 gg1(1, NT);   // layer 2:    N=128 -> 1

    // layer 0
    k_gemm_mma<128><<<gg2, 256>>>(0, b0);
    k_agg_relu128<<<gagg, 256>>>();
    // layer 1
    k_gemm_mma<128><<<gg2, 256>>>(1, b1);
    k_agg_relu128<<<gagg, 256>>>();
    // layer 2 (dim 64, agg after projection, fused log_softmax)
    k_gemm_mma<64><<<gg1, 256>>>(2, b2);
    k_agg_lsm64<<<gagg, 256>>>(out);
}

// round 16
// speedup vs baseline: 2.7316x; 1.0089x over previous
#include <cuda_runtime.h>
#include <cuda_fp16.h>
#include <cstdint>
#include <cmath>

#define NN 100000
#define NE 1600000
#define NT 782                 // ceil(NN/128)
#define NPAD (NT * 128)        // 100096
#define NBLK_SCAN ((NN + 1023) / 1024)   // 98
#define G0_BLOCKS (2 * NT)               // 1564 gemm blocks (layer 0)
#define SC_BLOCKS ((NE / 4 + 255) / 256) // 1563 scatter blocks

// ---------------- static device scratch ----------------
__device__ int   g_deg[NN];
__device__ int   g_rowoff[NN + 1];
__device__ int   g_cursor[NN];
__device__ int   g_csr[NE];
__device__ int   g_bsum[128];
__device__ float g_invdeg[NN];
__device__ float g_selfp[(size_t)NN * 64];            // layer-2 self projection, fp32
__device__ __half g_selfph[(size_t)NN * 128];         // layer-0/1 self projection, fp16
__device__ __half g_tmph[(size_t)NN * 128];           // neighbor projection, fp16
__device__ __half g_a[(size_t)NPAD * 128];            // activations fp16 (x, then h)
__device__ __half g_bw[3 * 256 * 128];                // weights [n][k] fp16, per layer

// ---------------- fused setup: zero_deg + convert_x + convert_w ----------
__global__ void k_setup(const float* __restrict__ x,
                        const float* __restrict__ Ws0, const float* __restrict__ Wn0,
                        const float* __restrict__ Ws1, const float* __restrict__ Wn1,
                        const float* __restrict__ Ws2, const float* __restrict__ Wn2) {
    int t = blockIdx.x * blockDim.x + threadIdx.x;
    if (t < NN) g_deg[t] = 0;
    if (t < 81920) {
        int layer, NO1, base;
        const float *Ws, *Wn;
        if (t < 32768)      { layer = 0; NO1 = 128; Ws = Ws0; Wn = Wn0; base = t; }
        else if (t < 65536) { layer = 1; NO1 = 128; Ws = Ws1; Wn = Wn1; base = t - 32768; }
        else                { layer = 2; NO1 = 64;  Ws = Ws2; Wn = Wn2; base = t - 65536; }
        int n = base >> 7, k = base & 127;
        float v = (n < NO1) ? Ws[k * NO1 + n] : Wn[k * NO1 + (n - NO1)];
        g_bw[layer * 32768 + base] = __float2half_rn(v);
    }
    size_t i = (size_t)t * 4;
    if (i < (size_t)NN * 128) {
        float4 v = *(const float4*)(x + i);
        uint2 p;
        __half2 h0 = __floats2half2_rn(v.x, v.y);
        __half2 h1 = __floats2half2_rn(v.z, v.w);
        p.x = *reinterpret_cast<uint32_t*>(&h0);
        p.y = *reinterpret_cast<uint32_t*>(&h1);
        *(uint2*)(g_a + i) = p;
    }
}

// ---------------- CSR preprocessing ----------------
__global__ void k_hist(const int* __restrict__ dst) {
    int e4 = blockIdx.x * blockDim.x + threadIdx.x;
    if (e4 < NE / 4) {
        int4 d = ((const int4*)dst)[e4];
        atomicAdd(&g_deg[d.x], 1);
        atomicAdd(&g_deg[d.y], 1);
        atomicAdd(&g_deg[d.z], 1);
        atomicAdd(&g_deg[d.w], 1);
    }
}
__global__ void k_scan_partial() {
    __shared__ int wsum[8];
    int t = threadIdx.x;
    int base = blockIdx.x * 1024 + t * 4;
    int s = 0;
#pragma unroll
    for (int i = 0; i < 4; i++) { int idx = base + i; if (idx < NN) s += g_deg[idx]; }
#pragma unroll
    for (int o = 16; o; o >>= 1) s += __shfl_xor_sync(0xffffffffu, s, o);
    if ((t & 31) == 0) wsum[t >> 5] = s;
    __syncthreads();
    if (t == 0) {
        int tot = 0;
#pragma unroll
        for (int i = 0; i < 8; i++) tot += wsum[i];
        g_bsum[blockIdx.x] = tot;
    }
}
__global__ void k_scan_bsums() {
    __shared__ int ws[4];
    int t = threadIdx.x, lane = t & 31, wid = t >> 5;
    int v = (t < NBLK_SCAN) ? g_bsum[t] : 0;
    int inc = v;
#pragma unroll
    for (int o = 1; o < 32; o <<= 1) {
        int y = __shfl_up_sync(0xffffffffu, inc, o);
        if (lane >= o) inc += y;
    }
    if (lane == 31) ws[wid] = inc;
    __syncthreads();
    if (t == 0) {
        int acc = 0;
#pragma unroll
        for (int i = 0; i < 4; i++) { int x = ws[i]; ws[i] = acc; acc += x; }
    }
    __syncthreads();
    if (t < NBLK_SCAN) g_bsum[t] = ws[wid] + inc - v;
}
__global__ void k_scan_final() {
    __shared__ int wsum[8];
    int t = threadIdx.x;
    int base = blockIdx.x * 1024 + t * 4;
    int v[4];
    int s = 0;
#pragma unroll
    for (int i = 0; i < 4; i++) {
        int idx = base + i;
        v[i] = (idx < NN) ? g_deg[idx] : 0;
        s += v[i];
    }
    int lane = t & 31, wid = t >> 5;
    int inc = s;
#pragma unroll
    for (int o = 1; o < 32; o <<= 1) {
        int y = __shfl_up_sync(0xffffffffu, inc, o);
        if (lane >= o) inc += y;
    }
    if (lane == 31) wsum[wid] = inc;
    __syncthreads();
    if (t == 0) {
        int acc = 0;
#pragma unroll
        for (int i = 0; i < 8; i++) { int x = wsum[i]; wsum[i] = acc; acc += x; }
    }
    __syncthreads();
    int excl = g_bsum[blockIdx.x] + wsum[wid] + (inc - s);
#pragma unroll
    for (int i = 0; i < 4; i++) {
        int idx = base + i;
        if (idx < NN) {
            g_rowoff[idx] = excl;
            g_cursor[idx] = excl;
            g_invdeg[idx] = 1.0f / fmaxf((float)v[i], 1.0f);
            excl += v[i];
        }
    }
    if (blockIdx.x == 0 && t == 0) g_rowoff[NN] = NE;
}

// ---------------- mma.sync / cp.async helpers ----------------
__device__ __forceinline__ uint32_t smem_u32(const void* p) {
    uint32_t a;
    asm("{ .reg .u64 t; cvta.to.shared.u64 t, %1; cvt.u32.u64 %0, t; }" : "=r"(a) : "l"(p));
    return a;
}
__device__ __forceinline__ void ldm_x4(uint32_t& d0, uint32_t& d1, uint32_t& d2, uint32_t& d3,
                                       uint32_t addr) {
    asm volatile("ldmatrix.sync.aligned.m8n8.x4.shared.b16 {%0,%1,%2,%3}, [%4];"
        : "=r"(d0), "=r"(d1), "=r"(d2), "=r"(d3) : "r"(addr));
}
__device__ __forceinline__ void mma_f16(float* c, const uint32_t* a, uint32_t b0, uint32_t b1) {
    asm volatile("mma.sync.aligned.m16n8k16.row.col.f32.f16.f16.f32 "
        "{%0,%1,%2,%3}, {%4,%5,%6,%7}, {%8,%9}, {%0,%1,%2,%3};"
        : "+f"(c[0]), "+f"(c[1]), "+f"(c[2]), "+f"(c[3])
        : "r"(a[0]), "r"(a[1]), "r"(a[2]), "r"(a[3]), "r"(b0), "r"(b1));
}
__device__ __forceinline__ void cp16(uint32_t dst, const void* src) {
    asm volatile("cp.async.cg.shared.global [%0], [%1], 16;" :: "r"(dst), "l"(src) : "memory");
}
#define CP_COMMIT() asm volatile("cp.async.commit_group;" ::: "memory")
#define CP_WAIT1()  asm volatile("cp.async.wait_group 1;" ::: "memory")
#define CP_WAIT0()  asm volatile("cp.async.wait_group 0;" ::: "memory")

// ---------------- GEMM tile body ----------
template <int NO1>
__device__ __forceinline__ void gemm_tile(int layer, const float* __restrict__ bias,
                                          int bn0, int tile, char* smem) {
    constexpr int STG = 16384;
    constexpr int A_S = 0, B_S = 8192;
    uint32_t sb = smem_u32(smem);
    int tid = threadIdx.x, wid = tid >> 5, lane = tid & 31;

    const __half* ap = g_a + (size_t)tile * 16384;
    const __half* bw = g_bw + layer * 32768 + (size_t)bn0 * 128;

    int wm = (wid & 3) * 32;
    int wn = (wid >> 2) * 64;
    int lrow = lane & 15, lchunk = lane >> 4;

    auto load_stage = [&](int kc, uint32_t sbase) {
#pragma unroll
        for (int ii = 0; ii < 2; ii++) {
            int i = tid + ii * 256;
            int r = i >> 2, c = i & 3;
            uint32_t off = (uint32_t)r * 64u + (uint32_t)((c ^ ((r >> 1) & 3)) << 4);
            cp16(sb + sbase + A_S + off, ap + r * 128 + kc * 32 + c * 8);
        }
#pragma unroll
        for (int ii = 0; ii < 2; ii++) {
            int i = tid + ii * 256;
            int r = i >> 2, c = i & 3;
            uint32_t off = (uint32_t)r * 64u + (uint32_t)((c ^ ((r >> 1) & 3)) << 4);
            cp16(sb + sbase + B_S + off, bw + r * 128 + kc * 32 + c * 8);
        }
    };

    float acc[2][8][4];
#pragma unroll
    for (int i = 0; i < 2; i++)
#pragma unroll
        for (int j = 0; j < 8; j++)
#pragma unroll
            for (int q = 0; q < 4; q++) acc[i][j][q] = 0.0f;

    load_stage(0, 0);
    CP_COMMIT();

#pragma unroll
    for (int kc = 0; kc < 4; kc++) {
        uint32_t cur = (uint32_t)(kc & 1) * STG;
        if (kc < 3) {
            load_stage(kc + 1, (uint32_t)((kc + 1) & 1) * STG);
            CP_COMMIT();
            CP_WAIT1();
        } else {
            CP_WAIT0();
        }
        __syncthreads();

#pragma unroll
        for (int ks = 0; ks < 2; ks++) {
            int c0 = 2 * ks;
            uint32_t av[2][4];
#pragma unroll
            for (int mt = 0; mt < 2; mt++) {
                int r = wm + mt * 16 + lrow;
                uint32_t off = (uint32_t)r * 64u
                             + (uint32_t)(((c0 + lchunk) ^ ((r >> 1) & 3)) << 4);
                ldm_x4(av[mt][0], av[mt][1], av[mt][2], av[mt][3], sb + cur + A_S + off);
            }
            uint32_t bv[8][2];
#pragma unroll
            for (int nq = 0; nq < 4; nq++) {
                int r = wn + nq * 16 + lrow;
                uint32_t off = (uint32_t)r * 64u
                             + (uint32_t)(((c0 + lchunk) ^ ((r >> 1) & 3)) << 4);
                uint32_t t0, t1, t2, t3;
                ldm_x4(t0, t1, t2, t3, sb + cur + B_S + off);
                bv[2 * nq][0] = t0; bv[2 * nq][1] = t2;
                bv[2 * nq + 1][0] = t1; bv[2 * nq + 1][1] = t3;
            }
#pragma unroll
            for (int mt = 0; mt < 2; mt++)
#pragma unroll
                for (int nt = 0; nt < 8; nt++)
                    mma_f16(acc[mt][nt], av[mt], bv[nt][0], bv[nt][1]);
        }
        __syncthreads();
    }

    int qrow = lane >> 2;
    int qcol = (lane & 3) * 2;
#pragma unroll
    for (int mt = 0; mt < 2; mt++) {
#pragma unroll
        for (int nt = 0; nt < 8; nt++) {
            int r0 = tile * 128 + wm + mt * 16 + qrow;
            int gc = bn0 + wn + nt * 8 + qcol;
            float2 v0 = make_float2(acc[mt][nt][0], acc[mt][nt][1]);
            float2 v1 = make_float2(acc[mt][nt][2], acc[mt][nt][3]);
            if (gc < NO1) {
                float2 bv = *(const float2*)(bias + gc);
                v0.x += bv.x; v0.y += bv.y;
                v1.x += bv.x; v1.y += bv.y;
                if (NO1 == 128) {
                    if (r0 < NN)
                        *(__half2*)(g_selfph + (size_t)r0 * 128 + gc) = __floats2half2_rn(v0.x, v0.y);
                    if (r0 + 8 < NN)
                        *(__half2*)(g_selfph + (size_t)(r0 + 8) * 128 + gc) = __floats2half2_rn(v1.x, v1.y);
                } else {
                    if (r0 < NN)     *(float2*)(g_selfp + (size_t)r0 * NO1 + gc) = v0;
                    if (r0 + 8 < NN) *(float2*)(g_selfp + (size_t)(r0 + 8) * NO1 + gc) = v1;
                }
            } else {
                int tc = gc - NO1;
                if (r0 < NN)
                    *(__half2*)(g_tmph + (size_t)r0 * NO1 + tc) = __floats2half2_rn(v0.x, v0.y);
                if (r0 + 8 < NN)
                    *(__half2*)(g_tmph + (size_t)(r0 + 8) * NO1 + tc) = __floats2half2_rn(v1.x, v1.y);
            }
        }
    }
}

// standalone GEMM (layers 1, 2)
template <int NO1>
__global__ __launch_bounds__(256) void k_gemm_mma(int layer, const float* __restrict__ bias) {
    __shared__ __align__(16) char smem[32768];
    gemm_tile<NO1>(layer, bias, blockIdx.x * 128, blockIdx.y, smem);
}

// fused layer-0 GEMM + CSR scatter (whole-block branching, parity-interleaved)
__global__ __launch_bounds__(256) void k_gemm0_scatter(const float* __restrict__ bias,
                                                       const int* __restrict__ src,
                                                       const int* __restrict__ dst) {
    __shared__ __align__(16) char smem[32768];
    int b = blockIdx.x;
    if ((b & 1) == 0) {
        int g = b >> 1;                 // 0 .. G0_BLOCKS-1 (grid sized so this holds)
        gemm_tile<128>(0, bias, (g & 1) * 128, g >> 1, smem);
    } else {
        int sc = b >> 1;                // 0 .. G0_BLOCKS-1
        if (sc < SC_BLOCKS) {
            int e4 = sc * 256 + threadIdx.x;
            if (e4 < NE / 4) {
                int4 sv = ((const int4*)src)[e4];
                int4 dv = ((const int4*)dst)[e4];
                g_csr[atomicAdd(&g_cursor[dv.x], 1)] = sv.x;
                g_csr[atomicAdd(&g_cursor[dv.y], 1)] = sv.y;
                g_csr[atomicAdd(&g_cursor[dv.z], 1)] = sv.z;
                g_csr[atomicAdd(&g_cursor[dv.w], 1)] = sv.w;
            }
        }
    }
}

// ---------------- aggregation (fp16 gather, fp32 accumulate, 8-wide MLP) ----------------
__device__ __forceinline__ void add_h4(float4& a, uint2 v) {
    __half2 p0 = *reinterpret_cast<__half2*>(&v.x);
    __half2 p1 = *reinterpret_cast<__half2*>(&v.y);
    float2 f0 = __half22float2(p0), f1 = __half22float2(p1);
    a.x += f0.x; a.y += f0.y; a.z += f1.x; a.w += f1.y;
}

__global__ __launch_bounds__(256) void k_agg_relu128() {
    int w = (blockIdx.x * blockDim.x + threadIdx.x) >> 5;
    int lane = threadIdx.x & 31;
    if (w >= NN) return;
    int beg = g_rowoff[w], end = g_rowoff[w + 1];
    float4 acc0 = make_float4(0.f, 0.f, 0.f, 0.f);
    float4 acc1 = make_float4(0.f, 0.f, 0.f, 0.f);
    int i = beg;
    for (; i + 7 < end; i += 8) {
        int u[8];
#pragma unroll
        for (int j = 0; j < 8; j++) u[j] = g_csr[i + j];
        uint2 v[8];
#pragma unroll
        for (int j = 0; j < 8; j++)
            v[j] = *(const uint2*)(g_tmph + (size_t)u[j] * 128 + lane * 4);
#pragma unroll
        for (int j = 0; j < 8; j++) add_h4((j & 1) ? acc1 : acc0, v[j]);
    }
    for (; i + 1 < end; i += 2) {
        int u0 = g_csr[i], u1 = g_csr[i + 1];
        uint2 v0 = *(const uint2*)(g_tmph + (size_t)u0 * 128 + lane * 4);
        uint2 v1 = *(const uint2*)(g_tmph + (size_t)u1 * 128 + lane * 4);
        add_h4(acc0, v0); add_h4(acc1, v1);
    }
    if (i < end) {
        int u0 = g_csr[i];
        uint2 v0 = *(const uint2*)(g_tmph + (size_t)u0 * 128 + lane * 4);
        add_h4(acc0, v0);
    }
    float s = g_invdeg[w];
    float4 sp;
    {
        uint2 spv = *(const uint2*)(g_selfph + (size_t)w * 128 + lane * 4);
        __half2 p0 = *reinterpret_cast<__half2*>(&spv.x);
        __half2 p1 = *reinterpret_cast<__half2*>(&spv.y);
        float2 f0 = __half22float2(p0), f1 = __half22float2(p1);
        sp = make_float4(f0.x, f0.y, f1.x, f1.y);
    }
    float4 o;
    o.x = fmaxf(fmaf(acc0.x + acc1.x, s, sp.x), 0.f);
    o.y = fmaxf(fmaf(acc0.y + acc1.y, s, sp.y), 0.f);
    o.z = fmaxf(fmaf(acc0.z + acc1.z, s, sp.z), 0.f);
    o.w = fmaxf(fmaf(acc0.w + acc1.w, s, sp.w), 0.f);
    uint2 p;
    __half2 h0 = __floats2half2_rn(o.x, o.y);
    __half2 h1 = __floats2half2_rn(o.z, o.w);
    p.x = *reinterpret_cast<uint32_t*>(&h0);
    p.y = *reinterpret_cast<uint32_t*>(&h1);
    *(uint2*)(g_a + (size_t)w * 128 + lane * 4) = p;
}

__global__ __launch_bounds__(256) void k_agg_lsm64(float* __restrict__ out) {
    int w = (blockIdx.x * blockDim.x + threadIdx.x) >> 5;
    int lane = threadIdx.x & 31;
    if (w >= NN) return;
    int beg = g_rowoff[w], end = g_rowoff[w + 1];
    float2 acc0 = make_float2(0.f, 0.f);
    float2 acc1 = make_float2(0.f, 0.f);
    int i = beg;
    for (; i + 7 < end; i += 8) {
        int u[8];
#pragma unroll
        for (int j = 0; j < 8; j++) u[j] = g_csr[i + j];
        __half2 v[8];
#pragma unroll
        for (int j = 0; j < 8; j++)
            v[j] = *(const __half2*)(g_tmph + (size_t)u[j] * 64 + lane * 2);
#pragma unroll
        for (int j = 0; j < 8; j++) {
            float2 f = __half22float2(v[j]);
            if (j & 1) { acc1.x += f.x; acc1.y += f.y; }
            else       { acc0.x += f.x; acc0.y += f.y; }
        }
    }
    for (; i < end; i++) {
        int u0 = g_csr[i];
        float2 f0 = __half22float2(*(const __half2*)(g_tmph + (size_t)u0 * 64 + lane * 2));
        acc0.x += f0.x; acc0.y += f0.y;
    }
    float s = g_invdeg[w];
    float2 sp = *(const float2*)(g_selfp + (size_t)w * 64 + lane * 2);
    float v0 = fmaf(acc0.x + acc1.x, s, sp.x);
    float v1 = fmaf(acc0.y + acc1.y, s, sp.y);
    float m = fmaxf(v0, v1);
#pragma unroll
    for (int o = 16; o; o >>= 1) m = fmaxf(m, __shfl_xor_sync(0xffffffffu, m, o));
    float e = expf(v0 - m) + expf(v1 - m);
#pragma unroll
    for (int o = 16; o; o >>= 1) e += __shfl_xor_sync(0xffffffffu, e, o);
    float lse = m + logf(e);
    float2 res = make_float2(v0 - lse, v1 - lse);
    *(float2*)(out + (size_t)w * 64 + lane * 2) = res;
}

// ---------------- launch: PURE kernel launches, zero other host API ----------------
extern "C" void kernel_launch(void* const* d_in, const int* in_sizes, int n_in,
                              void* d_out, int out_size) {
    const float* x   = (const float*)d_in[0];
    const int*   src = (const int*)d_in[1];
    const int*   dst = (const int*)d_in[2];
    const float* Ws0 = (const float*)d_in[3];
    const float* Wn0 = (const float*)d_in[4];
    const float* b0  = (const float*)d_in[5];
    const float* Ws1 = (const float*)d_in[6];
    const float* Wn1 = (const float*)d_in[7];
    const float* b1  = (const float*)d_in[8];
    const float* Ws2 = (const float*)d_in[9];
    const float* Wn2 = (const float*)d_in[10];
    const float* b2  = (const float*)d_in[11];
    float* out = (float*)d_out;

    // --- fused setup (zero_deg + convert_x + convert_w) ---
    k_setup<<<(NN * 128 / 4 + 255) / 256, 256>>>(x, Ws0, Wn0, Ws1, Wn1, Ws2, Wn2);

    // --- CSR build ---
    k_hist<<<(NE / 4 + 255) / 256, 256>>>(dst);
    k_scan_partial<<<NBLK_SCAN, 256>>>();
    k_scan_bsums<<<1, 128>>>();
    k_scan_final<<<NBLK_SCAN, 256>>>();

    dim3 gagg((NN + 7) / 8, 1);
    dim3 gg2(2, NT);
    dim3 gg1(1, NT);

    // --- fused layer-0 GEMM + scatter, parity interleaved ---
    k_gemm0_scatter<<<2 * G0_BLOCKS, 256>>>(b0, src, dst);
    k_agg_relu128<<<gagg, 256>>>();

    // layer 1
    k_gemm_mma<128><<<gg2, 256>>>(1, b1);
    k_agg_relu128<<<gagg, 256>>>();
    // layer 2
    k_gemm_mma<64><<<gg1, 256>>>(2, b2);
    k_agg_lsm64<<<gagg, 256>>>(out);
}

// round 17
// speedup vs baseline: 2.7941x; 1.0229x over previous
#include <cuda_runtime.h>
#include <cuda_fp16.h>
#include <cstdint>
#include <cmath>

#define NN 100000
#define NE 1600000
#define NT 782                 // ceil(NN/128)
#define NPAD (NT * 128)        // 100096
#define NBLK_SCAN ((NN + 1023) / 1024)   // 98
#define SC_BLOCKS ((NE / 4 + 255) / 256) // 1563 scatter blocks

// ---------------- static device scratch ----------------
__device__ int   g_deg[NN];
__device__ int   g_rowoff[NN + 1];
__device__ int   g_cursor[NN];
__device__ int   g_csr[NE];
__device__ int   g_bsum[128];
__device__ float g_invdeg[NN];
__device__ float g_selfp[(size_t)NN * 64];            // layer-2 self projection, fp32
__device__ __half g_selfph[(size_t)NN * 128];         // layer-0/1 self projection, fp16
__device__ __half g_tmph[(size_t)NN * 128];           // neighbor projection, fp16
__device__ __half g_a[(size_t)NPAD * 128];            // activations fp16 (x, then h)
__device__ __half g_bw[3 * 256 * 128];                // weights [n][k] fp16, per layer

// ---------------- fused setup: zero_deg + convert_x + convert_w ----------
__global__ void k_setup(const float* __restrict__ x,
                        const float* __restrict__ Ws0, const float* __restrict__ Wn0,
                        const float* __restrict__ Ws1, const float* __restrict__ Wn1,
                        const float* __restrict__ Ws2, const float* __restrict__ Wn2) {
    int t = blockIdx.x * blockDim.x + threadIdx.x;
    if (t < NN) g_deg[t] = 0;
    if (t < 81920) {
        int layer, NO1, base;
        const float *Ws, *Wn;
        if (t < 32768)      { layer = 0; NO1 = 128; Ws = Ws0; Wn = Wn0; base = t; }
        else if (t < 65536) { layer = 1; NO1 = 128; Ws = Ws1; Wn = Wn1; base = t - 32768; }
        else                { layer = 2; NO1 = 64;  Ws = Ws2; Wn = Wn2; base = t - 65536; }
        int n = base >> 7, k = base & 127;
        float v = (n < NO1) ? Ws[k * NO1 + n] : Wn[k * NO1 + (n - NO1)];
        g_bw[layer * 32768 + base] = __float2half_rn(v);
    }
    size_t i = (size_t)t * 4;
    if (i < (size_t)NN * 128) {
        float4 v = *(const float4*)(x + i);
        uint2 p;
        __half2 h0 = __floats2half2_rn(v.x, v.y);
        __half2 h1 = __floats2half2_rn(v.z, v.w);
        p.x = *reinterpret_cast<uint32_t*>(&h0);
        p.y = *reinterpret_cast<uint32_t*>(&h1);
        *(uint2*)(g_a + i) = p;
    }
}

// ---------------- CSR preprocessing ----------------
__global__ void k_hist(const int* __restrict__ dst) {
    int e4 = blockIdx.x * blockDim.x + threadIdx.x;
    if (e4 < NE / 4) {
        int4 d = ((const int4*)dst)[e4];
        atomicAdd(&g_deg[d.x], 1);
        atomicAdd(&g_deg[d.y], 1);
        atomicAdd(&g_deg[d.z], 1);
        atomicAdd(&g_deg[d.w], 1);
    }
}
__global__ void k_scan_partial() {
    __shared__ int wsum[8];
    int t = threadIdx.x;
    int base = blockIdx.x * 1024 + t * 4;
    int s = 0;
#pragma unroll
    for (int i = 0; i < 4; i++) { int idx = base + i; if (idx < NN) s += g_deg[idx]; }
#pragma unroll
    for (int o = 16; o; o >>= 1) s += __shfl_xor_sync(0xffffffffu, s, o);
    if ((t & 31) == 0) wsum[t >> 5] = s;
    __syncthreads();
    if (t == 0) {
        int tot = 0;
#pragma unroll
        for (int i = 0; i < 8; i++) tot += wsum[i];
        g_bsum[blockIdx.x] = tot;
    }
}
// scan_final computes its own prefix over raw bsum partials (no scan_bsums launch)
__global__ void k_scan_final() {
    __shared__ int wsum[8];
    __shared__ int base_s;
    int t = threadIdx.x;
    // warp 0: prefix of raw partials for blocks < blockIdx.x
    if (t < 32) {
        int p = 0;
        for (int j = t; j < blockIdx.x; j += 32) p += g_bsum[j];
#pragma unroll
        for (int o = 16; o; o >>= 1) p += __shfl_xor_sync(0xffffffffu, p, o);
        if (t == 0) base_s = p;
    }
    int base = blockIdx.x * 1024 + t * 4;
    int v[4];
    int s = 0;
#pragma unroll
    for (int i = 0; i < 4; i++) {
        int idx = base + i;
        v[i] = (idx < NN) ? g_deg[idx] : 0;
        s += v[i];
    }
    int lane = t & 31, wid = t >> 5;
    int inc = s;
#pragma unroll
    for (int o = 1; o < 32; o <<= 1) {
        int y = __shfl_up_sync(0xffffffffu, inc, o);
        if (lane >= o) inc += y;
    }
    if (lane == 31) wsum[wid] = inc;
    __syncthreads();
    if (t == 0) {
        int acc = 0;
#pragma unroll
        for (int i = 0; i < 8; i++) { int x = wsum[i]; wsum[i] = acc; acc += x; }
    }
    __syncthreads();
    int excl = base_s + wsum[wid] + (inc - s);
#pragma unroll
    for (int i = 0; i < 4; i++) {
        int idx = base + i;
        if (idx < NN) {
            g_rowoff[idx] = excl;
            g_cursor[idx] = excl;
            g_invdeg[idx] = 1.0f / fmaxf((float)v[i], 1.0f);
            excl += v[i];
        }
    }
    if (blockIdx.x == 0 && t == 0) g_rowoff[NN] = NE;
}

// ---------------- mma.sync / cp.async helpers ----------------
__device__ __forceinline__ uint32_t smem_u32(const void* p) {
    uint32_t a;
    asm("{ .reg .u64 t; cvta.to.shared.u64 t, %1; cvt.u32.u64 %0, t; }" : "=r"(a) : "l"(p));
    return a;
}
__device__ __forceinline__ void ldm_x4(uint32_t& d0, uint32_t& d1, uint32_t& d2, uint32_t& d3,
                                       uint32_t addr) {
    asm volatile("ldmatrix.sync.aligned.m8n8.x4.shared.b16 {%0,%1,%2,%3}, [%4];"
        : "=r"(d0), "=r"(d1), "=r"(d2), "=r"(d3) : "r"(addr));
}
__device__ __forceinline__ void mma_f16(float* c, const uint32_t* a, uint32_t b0, uint32_t b1) {
    asm volatile("mma.sync.aligned.m16n8k16.row.col.f32.f16.f16.f32 "
        "{%0,%1,%2,%3}, {%4,%5,%6,%7}, {%8,%9}, {%0,%1,%2,%3};"
        : "+f"(c[0]), "+f"(c[1]), "+f"(c[2]), "+f"(c[3])
        : "r"(a[0]), "r"(a[1]), "r"(a[2]), "r"(a[3]), "r"(b0), "r"(b1));
}
__device__ __forceinline__ void cp16(uint32_t dst, const void* src) {
    asm volatile("cp.async.cg.shared.global [%0], [%1], 16;" :: "r"(dst), "l"(src) : "memory");
}
#define CP_COMMIT() asm volatile("cp.async.commit_group;" ::: "memory")
#define CP_WAIT1()  asm volatile("cp.async.wait_group 1;" ::: "memory")
#define CP_WAIT0()  asm volatile("cp.async.wait_group 0;" ::: "memory")

// ---------------- A-resident GEMM tile body ----------
// A tile (128x128 fp16, 32KB) resident in SMEM; B streamed per strip through a
// 2-stage 8KB ping-pong. CTA computes ALL strips of its row tile.
// A rows: 256B = 16 chunks; chunk c of row r at r*256 + ((c ^ (r&7))*16).
// B rows: 64B  = 4 chunks;  chunk c of row r at r*64  + ((c ^ ((r>>1)&3))*16).
template <int NO1, int NSTRIPS>
__device__ __forceinline__ void gemm_tile(int layer, const float* __restrict__ bias,
                                          int tile, char* smem) {
    constexpr int A_S = 0;            // 32KB
    constexpr int B_S = 32768;        // 2 x 8KB
    constexpr int BSTG = 8192;
    uint32_t sb = smem_u32(smem);
    int tid = threadIdx.x, wid = tid >> 5, lane = tid & 31;

    const __half* ap = g_a + (size_t)tile * 16384;
    const __half* bwbase = g_bw + layer * 32768;

    int wm = (wid & 3) * 32;
    int wn = (wid >> 2) * 64;
    int lrow = lane & 15, lchunk = lane >> 4;

    // load full A (2048 chunks)
#pragma unroll
    for (int ii = 0; ii < 8; ii++) {
        int i = tid + ii * 256;
        int r = i >> 4, c = i & 15;
        uint32_t off = (uint32_t)r * 256u + (uint32_t)((c ^ (r & 7)) << 4);
        cp16(sb + A_S + off, ap + r * 128 + c * 8);
    }

    auto load_b = [&](const __half* bw, int kc, uint32_t sbase) {
#pragma unroll
        for (int ii = 0; ii < 2; ii++) {
            int i = tid + ii * 256;
            int r = i >> 2, c = i & 3;
            uint32_t off = (uint32_t)r * 64u + (uint32_t)((c ^ ((r >> 1) & 3)) << 4);
            cp16(sb + sbase + off, bw + r * 128 + kc * 32 + c * 8);
        }
    };

    int qrow = lane >> 2;
    int qcol = (lane & 3) * 2;

#pragma unroll
    for (int s = 0; s < NSTRIPS; s++) {
        const __half* bw = bwbase + (size_t)(s * 128) * 128;

        float acc[2][8][4];
#pragma unroll
        for (int i = 0; i < 2; i++)
#pragma unroll
            for (int j = 0; j < 8; j++)
#pragma unroll
                for (int q = 0; q < 4; q++) acc[i][j][q] = 0.0f;

        load_b(bw, 0, B_S);             // group: (A if s==0) + B(kc0)
        CP_COMMIT();

#pragma unroll
        for (int kc = 0; kc < 4; kc++) {
            uint32_t cur = B_S + (uint32_t)(kc & 1) * BSTG;
            if (kc < 3) {
                load_b(bw, kc + 1, B_S + (uint32_t)((kc + 1) & 1) * BSTG);
                CP_COMMIT();
                CP_WAIT1();
            } else {
                CP_WAIT0();
            }
            __syncthreads();

#pragma unroll
            for (int ks = 0; ks < 2; ks++) {
                uint32_t av[2][4];
#pragma unroll
                for (int mt = 0; mt < 2; mt++) {
                    int r = wm + mt * 16 + lrow;
                    int clog = kc * 4 + ks * 2 + lchunk;   // 16 chunks across K
                    uint32_t off = (uint32_t)r * 256u
                                 + (uint32_t)((clog ^ (r & 7)) << 4);
                    ldm_x4(av[mt][0], av[mt][1], av[mt][2], av[mt][3], sb + A_S + off);
                }
                int c0 = 2 * ks;
                uint32_t bv[8][2];
#pragma unroll
                for (int nq = 0; nq < 4; nq++) {
                    int r = wn + nq * 16 + lrow;
                    uint32_t off = (uint32_t)r * 64u
                                 + (uint32_t)(((c0 + lchunk) ^ ((r >> 1) & 3)) << 4);
                    uint32_t t0, t1, t2, t3;
                    ldm_x4(t0, t1, t2, t3, sb + cur + off);
                    bv[2 * nq][0] = t0; bv[2 * nq][1] = t2;
                    bv[2 * nq + 1][0] = t1; bv[2 * nq + 1][1] = t3;
                }
#pragma unroll
                for (int mt = 0; mt < 2; mt++)
#pragma unroll
                    for (int nt = 0; nt < 8; nt++)
                        mma_f16(acc[mt][nt], av[mt], bv[nt][0], bv[nt][1]);
            }
            __syncthreads();
        }

        // epilogue for this strip
#pragma unroll
        for (int mt = 0; mt < 2; mt++) {
#pragma unroll
            for (int nt = 0; nt < 8; nt++) {
                int r0 = tile * 128 + wm + mt * 16 + qrow;
                int gc = s * 128 + wn + nt * 8 + qcol;
                float2 v0 = make_float2(acc[mt][nt][0], acc[mt][nt][1]);
                float2 v1 = make_float2(acc[mt][nt][2], acc[mt][nt][3]);
                if (gc < NO1) {
                    float2 bv = *(const float2*)(bias + gc);
                    v0.x += bv.x; v0.y += bv.y;
                    v1.x += bv.x; v1.y += bv.y;
                    if (NO1 == 128) {
                        if (r0 < NN)
                            *(__half2*)(g_selfph + (size_t)r0 * 128 + gc) = __floats2half2_rn(v0.x, v0.y);
                        if (r0 + 8 < NN)
                            *(__half2*)(g_selfph + (size_t)(r0 + 8) * 128 + gc) = __floats2half2_rn(v1.x, v1.y);
                    } else {
                        if (r0 < NN)     *(float2*)(g_selfp + (size_t)r0 * NO1 + gc) = v0;
                        if (r0 + 8 < NN) *(float2*)(g_selfp + (size_t)(r0 + 8) * NO1 + gc) = v1;
                    }
                } else {
                    int tc = gc - NO1;
                    if (r0 < NN)
                        *(__half2*)(g_tmph + (size_t)r0 * NO1 + tc) = __floats2half2_rn(v0.x, v0.y);
                    if (r0 + 8 < NN)
                        *(__half2*)(g_tmph + (size_t)(r0 + 8) * NO1 + tc) = __floats2half2_rn(v1.x, v1.y);
                }
            }
        }
    }
}

// standalone GEMM (layers 1, 2)
template <int NO1, int NSTRIPS>
__global__ __launch_bounds__(256) void k_gemm_mma(int layer, const float* __restrict__ bias) {
    __shared__ __align__(16) char smem[49152];
    gemm_tile<NO1, NSTRIPS>(layer, bias, blockIdx.x, smem);
}

// fused layer-0 GEMM + CSR scatter (whole-block branching, parity-interleaved)
// grid: 2*NT blocks (even=gemm tile b/2, odd=scatter b/2) + (SC_BLOCKS-NT) trailing scatter
__global__ __launch_bounds__(256) void k_gemm0_scatter(const float* __restrict__ bias,
                                                       const int* __restrict__ src,
                                                       const int* __restrict__ dst) {
    __shared__ __align__(16) char smem[49152];
    int b = blockIdx.x;
    if (b < 2 * NT && (b & 1) == 0) {
        gemm_tile<128, 2>(0, bias, b >> 1, smem);
    } else {
        int sc = (b < 2 * NT) ? (b >> 1) : (NT + (b - 2 * NT));
        if (sc < SC_BLOCKS) {
            int e4 = sc * 256 + threadIdx.x;
            if (e4 < NE / 4) {
                int4 sv = ((const int4*)src)[e4];
                int4 dv = ((const int4*)dst)[e4];
                g_csr[atomicAdd(&g_cursor[dv.x], 1)] = sv.x;
                g_csr[atomicAdd(&g_cursor[dv.y], 1)] = sv.y;
                g_csr[atomicAdd(&g_cursor[dv.z], 1)] = sv.z;
                g_csr[atomicAdd(&g_cursor[dv.w], 1)] = sv.w;
            }
        }
    }
}

// ---------------- aggregation (fp16 gather, fp32 accumulate, 8-wide MLP) ----------------
__device__ __forceinline__ void add_h4(float4& a, uint2 v) {
    __half2 p0 = *reinterpret_cast<__half2*>(&v.x);
    __half2 p1 = *reinterpret_cast<__half2*>(&v.y);
    float2 f0 = __half22float2(p0), f1 = __half22float2(p1);
    a.x += f0.x; a.y += f0.y; a.z += f1.x; a.w += f1.y;
}

__global__ __launch_bounds__(256) void k_agg_relu128() {
    int w = (blockIdx.x * blockDim.x + threadIdx.x) >> 5;
    int lane = threadIdx.x & 31;
    if (w >= NN) return;
    int beg = g_rowoff[w], end = g_rowoff[w + 1];
    float4 acc0 = make_float4(0.f, 0.f, 0.f, 0.f);
    float4 acc1 = make_float4(0.f, 0.f, 0.f, 0.f);
    int i = beg;
    for (; i + 7 < end; i += 8) {
        int u[8];
#pragma unroll
        for (int j = 0; j < 8; j++) u[j] = g_csr[i + j];
        uint2 v[8];
#pragma unroll
        for (int j = 0; j < 8; j++)
            v[j] = *(const uint2*)(g_tmph + (size_t)u[j] * 128 + lane * 4);
#pragma unroll
        for (int j = 0; j < 8; j++) add_h4((j & 1) ? acc1 : acc0, v[j]);
    }
    for (; i + 1 < end; i += 2) {
        int u0 = g_csr[i], u1 = g_csr[i + 1];
        uint2 v0 = *(const uint2*)(g_tmph + (size_t)u0 * 128 + lane * 4);
        uint2 v1 = *(const uint2*)(g_tmph + (size_t)u1 * 128 + lane * 4);
        add_h4(acc0, v0); add_h4(acc1, v1);
    }
    if (i < end) {
        int u0 = g_csr[i];
        uint2 v0 = *(const uint2*)(g_tmph + (size_t)u0 * 128 + lane * 4);
        add_h4(acc0, v0);
    }
    float s = g_invdeg[w];
    float4 sp;
    {
        uint2 spv = *(const uint2*)(g_selfph + (size_t)w * 128 + lane * 4);
        __half2 p0 = *reinterpret_cast<__half2*>(&spv.x);
        __half2 p1 = *reinterpret_cast<__half2*>(&spv.y);
        float2 f0 = __half22float2(p0), f1 = __half22float2(p1);
        sp = make_float4(f0.x, f0.y, f1.x, f1.y);
    }
    float4 o;
    o.x = fmaxf(fmaf(acc0.x + acc1.x, s, sp.x), 0.f);
    o.y = fmaxf(fmaf(acc0.y + acc1.y, s, sp.y), 0.f);
    o.z = fmaxf(fmaf(acc0.z + acc1.z, s, sp.z), 0.f);
    o.w = fmaxf(fmaf(acc0.w + acc1.w, s, sp.w), 0.f);
    uint2 p;
    __half2 h0 = __floats2half2_rn(o.x, o.y);
    __half2 h1 = __floats2half2_rn(o.z, o.w);
    p.x = *reinterpret_cast<uint32_t*>(&h0);
    p.y = *reinterpret_cast<uint32_t*>(&h1);
    *(uint2*)(g_a + (size_t)w * 128 + lane * 4) = p;
}

__global__ __launch_bounds__(256) void k_agg_lsm64(float* __restrict__ out) {
    int w = (blockIdx.x * blockDim.x + threadIdx.x) >> 5;
    int lane = threadIdx.x & 31;
    if (w >= NN) return;
    int beg = g_rowoff[w], end = g_rowoff[w + 1];
    float2 acc0 = make_float2(0.f, 0.f);
    float2 acc1 = make_float2(0.f, 0.f);
    int i = beg;
    for (; i + 7 < end; i += 8) {
        int u[8];
#pragma unroll
        for (int j = 0; j < 8; j++) u[j] = g_csr[i + j];
        __half2 v[8];
#pragma unroll
        for (int j = 0; j < 8; j++)
            v[j] = *(const __half2*)(g_tmph + (size_t)u[j] * 64 + lane * 2);
#pragma unroll
        for (int j = 0; j < 8; j++) {
            float2 f = __half22float2(v[j]);
            if (j & 1) { acc1.x += f.x; acc1.y += f.y; }
            else       { acc0.x += f.x; acc0.y += f.y; }
        }
    }
    for (; i < end; i++) {
        int u0 = g_csr[i];
        float2 f0 = __half22float2(*(const __half2*)(g_tmph + (size_t)u0 * 64 + lane * 2));
        acc0.x += f0.x; acc0.y += f0.y;
    }
    float s = g_invdeg[w];
    float2 sp = *(const float2*)(g_selfp + (size_t)w * 64 + lane * 2);
    float v0 = fmaf(acc0.x + acc1.x, s, sp.x);
    float v1 = fmaf(acc0.y + acc1.y, s, sp.y);
    float m = fmaxf(v0, v1);
#pragma unroll
    for (int o = 16; o; o >>= 1) m = fmaxf(m, __shfl_xor_sync(0xffffffffu, m, o));
    float e = expf(v0 - m) + expf(v1 - m);
#pragma unroll
    for (int o = 16; o; o >>= 1) e += __shfl_xor_sync(0xffffffffu, e, o);
    float lse = m + logf(e);
    float2 res = make_float2(v0 - lse, v1 - lse);
    *(float2*)(out + (size_t)w * 64 + lane * 2) = res;
}

// ---------------- launch: PURE kernel launches, zero other host API ----------------
extern "C" void kernel_launch(void* const* d_in, const int* in_sizes, int n_in,
                              void* d_out, int out_size) {
    const float* x   = (const float*)d_in[0];
    const int*   src = (const int*)d_in[1];
    const int*   dst = (const int*)d_in[2];
    const float* Ws0 = (const float*)d_in[3];
    const float* Wn0 = (const float*)d_in[4];
    const float* b0  = (const float*)d_in[5];
    const float* Ws1 = (const float*)d_in[6];
    const float* Wn1 = (const float*)d_in[7];
    const float* b1  = (const float*)d_in[8];
    const float* Ws2 = (const float*)d_in[9];
    const float* Wn2 = (const float*)d_in[10];
    const float* b2  = (const float*)d_in[11];
    float* out = (float*)d_out;

    // --- fused setup ---
    k_setup<<<(NN * 128 / 4 + 255) / 256, 256>>>(x, Ws0, Wn0, Ws1, Wn1, Ws2, Wn2);

    // --- CSR build (scan_final computes its own bsum prefix) ---
    k_hist<<<(NE / 4 + 255) / 256, 256>>>(dst);
    k_scan_partial<<<NBLK_SCAN, 256>>>();
    k_scan_final<<<NBLK_SCAN, 256>>>();

    dim3 gagg((NN + 7) / 8, 1);

    // --- fused layer-0 GEMM (A-resident, both strips) + scatter ---
    int total = 2 * NT + (SC_BLOCKS - NT);
    k_gemm0_scatter<<<total, 256>>>(b0, src, dst);
    k_agg_relu128<<<gagg, 256>>>();

    // layer 1
    k_gemm_mma<128, 2><<<NT, 256>>>(1, b1);
    k_agg_relu128<<<gagg, 256>>>();
    // layer 2
    k_gemm_mma<64, 1><<<NT, 256>>>(2, b2);
    k_agg_lsm64<<<gagg, 256>>>(out);
}